// round 2
// baseline (speedup 1.0000x reference)
#include <cuda_runtime.h>
#include <cuda_bf16.h>
#include <math.h>

// Problem constants
#define NX     768
#define NHEAD  12
#define DH     64
#define NCTX   2048
#define BATCH  4
#define MROWS  (BATCH * NCTX)        // 8192
#define EPS    1e-5f
#define NEGBIG -1000000000.0f

// ---------------- scratch (no allocations allowed) ----------------
__device__ float g_qkv [MROWS * 3 * NX];   // 8192 x 2304
__device__ float g_attn[MROWS * NX];       // attention output (merged heads)
__device__ float g_n   [MROWS * NX];       // LN1 output
__device__ float g_h   [MROWS * 4 * NX];   // MLP hidden
__device__ float g_tmp [MROWS * NX];       // proj / fc2 output

// =====================================================================
// GEMM: C[M,N] = A[M,K] @ B[K,N] + bias[N]   (optional ReLU)
// BM=BN=128, BK=8, 256 threads, 8x8 micro-tile per thread.
// All dims are multiples of tile sizes for this problem -> no bounds checks.
// =====================================================================
__global__ __launch_bounds__(256) void gemm_kernel(
    const float* __restrict__ A, const float* __restrict__ B,
    const float* __restrict__ bias, float* __restrict__ C,
    int M, int N, int K, int relu)
{
    __shared__ float As[8][132];   // transposed: As[k][row]
    __shared__ float Bs[8][128];

    const int tid = threadIdx.x;
    const int tx  = tid & 15;           // 0..15  (col group)
    const int ty  = tid >> 4;           // 0..15  (row group)
    const int row0 = blockIdx.y * 128;
    const int col0 = blockIdx.x * 128;

    // A-load mapping: each thread loads 4 consecutive k of one row
    const int arow = tid >> 1;              // 0..127
    const int acol = (tid & 1) * 4;         // 0 or 4
    // B-load mapping: each thread loads 4 consecutive n of one k-row
    const int brow = tid >> 5;              // 0..7
    const int bcol = (tid & 31) * 4;        // 0..124

    float acc[8][8];
#pragma unroll
    for (int i = 0; i < 8; i++)
#pragma unroll
        for (int j = 0; j < 8; j++) acc[i][j] = 0.0f;

    for (int kt = 0; kt < K; kt += 8) {
        float4 a4 = *reinterpret_cast<const float4*>(A + (size_t)(row0 + arow) * K + kt + acol);
        As[acol + 0][arow] = a4.x;
        As[acol + 1][arow] = a4.y;
        As[acol + 2][arow] = a4.z;
        As[acol + 3][arow] = a4.w;

        float4 b4 = *reinterpret_cast<const float4*>(B + (size_t)(kt + brow) * N + col0 + bcol);
        *reinterpret_cast<float4*>(&Bs[brow][bcol]) = b4;

        __syncthreads();

#pragma unroll
        for (int k = 0; k < 8; k++) {
            float a[8], b[8];
            float4 av0 = *reinterpret_cast<const float4*>(&As[k][ty * 8]);
            float4 av1 = *reinterpret_cast<const float4*>(&As[k][ty * 8 + 4]);
            a[0]=av0.x; a[1]=av0.y; a[2]=av0.z; a[3]=av0.w;
            a[4]=av1.x; a[5]=av1.y; a[6]=av1.z; a[7]=av1.w;
            float4 bv0 = *reinterpret_cast<const float4*>(&Bs[k][tx * 8]);
            float4 bv1 = *reinterpret_cast<const float4*>(&Bs[k][tx * 8 + 4]);
            b[0]=bv0.x; b[1]=bv0.y; b[2]=bv0.z; b[3]=bv0.w;
            b[4]=bv1.x; b[5]=bv1.y; b[6]=bv1.z; b[7]=bv1.w;
#pragma unroll
            for (int i = 0; i < 8; i++)
#pragma unroll
                for (int j = 0; j < 8; j++)
                    acc[i][j] = fmaf(a[i], b[j], acc[i][j]);
        }
        __syncthreads();
    }

    // epilogue
#pragma unroll
    for (int i = 0; i < 8; i++) {
        const int row = row0 + ty * 8 + i;
        float* cp = C + (size_t)row * N + col0 + tx * 8;
#pragma unroll
        for (int j = 0; j < 8; j++) {
            float v = acc[i][j] + bias[col0 + tx * 8 + j];
            if (relu) v = fmaxf(v, 0.0f);
            cp[j] = v;
        }
    }
}

// =====================================================================
// Flash attention (causal, NO 1/sqrt(d) scale, matching reference)
// qkv layout: [8192, 2304]; q at col h*64, k at 768+h*64, v at 1536+h*64
// BR=64 rows per block, BC=32 cols per tile, 256 threads.
// Thread layout for S (64x32): ty=tid/16 owns 4 rows, tx=tid%16 owns 2 cols.
// For O (64x64): same 4 rows, tx owns 4 dh-cols.
// =====================================================================
__global__ __launch_bounds__(256) void attn_kernel(
    const float* __restrict__ qkv, float* __restrict__ out)
{
    __shared__ float Qs[64][65];
    __shared__ float Ks[32][65];
    __shared__ float Vs[32][65];
    __shared__ float Ps[64][33];

    const int tid = threadIdx.x;
    const int tx = tid & 15;
    const int ty = tid >> 4;
    const int it = blockIdx.x;        // row tile (0..31)
    const int h  = blockIdx.y;
    const int b  = blockIdx.z;

    const int brow = b * NCTX + it * 64;   // global row of first Q row

    // load Q tile [64][64]
    for (int idx = tid; idx < 64 * 64; idx += 256) {
        int r = idx >> 6, d = idx & 63;
        Qs[r][d] = qkv[(size_t)(brow + r) * (3 * NX) + h * DH + d];
    }

    float o[4][4];
    float m[4], l[4];
#pragma unroll
    for (int i = 0; i < 4; i++) {
        m[i] = -INFINITY; l[i] = 0.0f;
#pragma unroll
        for (int j = 0; j < 4; j++) o[i][j] = 0.0f;
    }

    const int jmax = 2 * it + 1;
    for (int jt = 0; jt <= jmax; jt++) {
        // load K, V tiles [32][64]
        for (int idx = tid; idx < 32 * 64; idx += 256) {
            int r = idx >> 6, d = idx & 63;
            size_t base = (size_t)(b * NCTX + jt * 32 + r) * (3 * NX) + h * DH + d;
            Ks[r][d] = qkv[base + NX];
            Vs[r][d] = qkv[base + 2 * NX];
        }
        __syncthreads();

        // S = Q K^T for my 4x2 patch
        float s[4][2];
#pragma unroll
        for (int i = 0; i < 4; i++) { s[i][0] = 0.0f; s[i][1] = 0.0f; }
#pragma unroll 8
        for (int d = 0; d < 64; d++) {
            float q0 = Qs[ty * 4 + 0][d];
            float q1 = Qs[ty * 4 + 1][d];
            float q2 = Qs[ty * 4 + 2][d];
            float q3 = Qs[ty * 4 + 3][d];
            float k0 = Ks[tx * 2 + 0][d];
            float k1 = Ks[tx * 2 + 1][d];
            s[0][0] = fmaf(q0, k0, s[0][0]); s[0][1] = fmaf(q0, k1, s[0][1]);
            s[1][0] = fmaf(q1, k0, s[1][0]); s[1][1] = fmaf(q1, k1, s[1][1]);
            s[2][0] = fmaf(q2, k0, s[2][0]); s[2][1] = fmaf(q2, k1, s[2][1]);
            s[3][0] = fmaf(q3, k0, s[3][0]); s[3][1] = fmaf(q3, k1, s[3][1]);
        }

        // causal mask on diagonal tiles
        if (jt >= 2 * it) {
#pragma unroll
            for (int i = 0; i < 4; i++) {
                int gr = it * 64 + ty * 4 + i;
#pragma unroll
                for (int j = 0; j < 2; j++) {
                    int gc = jt * 32 + tx * 2 + j;
                    if (gc > gr) s[i][j] = NEGBIG;
                }
            }
        }

        // online softmax update
        float alpha[4];
#pragma unroll
        for (int i = 0; i < 4; i++) {
            float mt = fmaxf(s[i][0], s[i][1]);
#pragma unroll
            for (int off = 8; off > 0; off >>= 1)
                mt = fmaxf(mt, __shfl_xor_sync(0xffffffffu, mt, off));
            float mnew = fmaxf(m[i], mt);
            alpha[i] = __expf(m[i] - mnew);
            float p0 = __expf(s[i][0] - mnew);
            float p1 = __expf(s[i][1] - mnew);
            float ps = p0 + p1;
#pragma unroll
            for (int off = 8; off > 0; off >>= 1)
                ps += __shfl_xor_sync(0xffffffffu, ps, off);
            l[i] = l[i] * alpha[i] + ps;
            m[i] = mnew;
            Ps[ty * 4 + i][tx * 2 + 0] = p0;
            Ps[ty * 4 + i][tx * 2 + 1] = p1;
#pragma unroll
            for (int j = 0; j < 4; j++) o[i][j] *= alpha[i];
        }
        __syncthreads();   // Ps ready

        // O += P @ V   (my 4 rows x 4 dh-cols)
#pragma unroll 8
        for (int c = 0; c < 32; c++) {
            float v0 = Vs[c][tx * 4 + 0];
            float v1 = Vs[c][tx * 4 + 1];
            float v2 = Vs[c][tx * 4 + 2];
            float v3 = Vs[c][tx * 4 + 3];
#pragma unroll
            for (int i = 0; i < 4; i++) {
                float p = Ps[ty * 4 + i][c];
                o[i][0] = fmaf(p, v0, o[i][0]);
                o[i][1] = fmaf(p, v1, o[i][1]);
                o[i][2] = fmaf(p, v2, o[i][2]);
                o[i][3] = fmaf(p, v3, o[i][3]);
            }
        }
        __syncthreads();   // done reading Ks/Vs/Ps for this tile
    }

    // write merged-head output: out[row][h*64 + d]
#pragma unroll
    for (int i = 0; i < 4; i++) {
        float inv = 1.0f / l[i];
        float* op = out + (size_t)(brow + ty * 4 + i) * NX + h * DH + tx * 4;
#pragma unroll
        for (int j = 0; j < 4; j++) op[j] = o[i][j] * inv;
    }
}

// =====================================================================
// LayerNorm (additive form, faithful to source bug):
//   t = in1 + in2;  out = g + (t - mean)/sqrt(var + eps) + b
// one block (256 threads) per row of 768
// =====================================================================
__global__ __launch_bounds__(256) void ln_kernel(
    const float* __restrict__ in1, const float* __restrict__ in2,
    const float* __restrict__ g, const float* __restrict__ bb,
    float* __restrict__ out)
{
    __shared__ float buf[NX];
    __shared__ float red[256];
    __shared__ float red2[256];

    const int row = blockIdx.x;
    const int tid = threadIdx.x;
    const size_t base = (size_t)row * NX;

    float s = 0.0f, s2 = 0.0f;
#pragma unroll
    for (int k = 0; k < 3; k++) {
        int i = tid + k * 256;
        float v = in1[base + i] + in2[base + i];
        buf[i] = v;
        s += v; s2 += v * v;
    }
    red[tid] = s; red2[tid] = s2;
    __syncthreads();
    for (int off = 128; off > 0; off >>= 1) {
        if (tid < off) { red[tid] += red[tid + off]; red2[tid] += red2[tid + off]; }
        __syncthreads();
    }
    const float u = red[0] * (1.0f / NX);
    const float var = red2[0] * (1.0f / NX) - u * u;
    const float rstd = rsqrtf(var + EPS);
#pragma unroll
    for (int k = 0; k < 3; k++) {
        int i = tid + k * 256;
        out[base + i] = g[i] + (buf[i] - u) * rstd + bb[i];
    }
}

// =====================================================================
extern "C" void kernel_launch(void* const* d_in, const int* in_sizes, int n_in,
                              void* d_out, int out_size)
{
    const float* x      = (const float*)d_in[0];
    const float* w_attn = (const float*)d_in[1];
    const float* b_attn = (const float*)d_in[2];
    const float* w_proj = (const float*)d_in[3];
    const float* b_proj = (const float*)d_in[4];
    const float* ln1_g  = (const float*)d_in[5];
    const float* ln1_b  = (const float*)d_in[6];
    const float* w_fc   = (const float*)d_in[7];
    const float* b_fc   = (const float*)d_in[8];
    const float* w_fc2  = (const float*)d_in[9];
    const float* b_fc2  = (const float*)d_in[10];
    const float* ln2_g  = (const float*)d_in[11];
    const float* ln2_b  = (const float*)d_in[12];
    float* out = (float*)d_out;

    float *qkv, *attn, *nbuf, *hbuf, *tmp;
    cudaGetSymbolAddress((void**)&qkv,  g_qkv);
    cudaGetSymbolAddress((void**)&attn, g_attn);
    cudaGetSymbolAddress((void**)&nbuf, g_n);
    cudaGetSymbolAddress((void**)&hbuf, g_h);
    cudaGetSymbolAddress((void**)&tmp,  g_tmp);

    // 1. qkv = x @ w_attn + b_attn            [8192, 2304]
    gemm_kernel<<<dim3(3 * NX / 128, MROWS / 128), 256>>>(
        x, w_attn, b_attn, qkv, MROWS, 3 * NX, NX, 0);

    // 2. attention (causal, unscaled)          -> attn [8192, 768]
    attn_kernel<<<dim3(NCTX / 64, NHEAD, BATCH), 256>>>(qkv, attn);

    // 3. proj = attn @ w_proj + b_proj         -> tmp
    gemm_kernel<<<dim3(NX / 128, MROWS / 128), 256>>>(
        attn, w_proj, b_proj, tmp, MROWS, NX, NX, 0);

    // 4. n = LN(x + proj)
    ln_kernel<<<MROWS, 256>>>(x, tmp, ln1_g, ln1_b, nbuf);

    // 5. h = relu(n @ w_fc + b_fc)             [8192, 3072]
    gemm_kernel<<<dim3(4 * NX / 128, MROWS / 128), 256>>>(
        nbuf, w_fc, b_fc, hbuf, MROWS, 4 * NX, NX, 1);

    // 6. m = h @ w_fc2 + b_fc2                 -> tmp
    gemm_kernel<<<dim3(NX / 128, MROWS / 128), 256>>>(
        hbuf, w_fc2, b_fc2, tmp, MROWS, NX, 4 * NX, 0);

    // 7. out = LN(n + m)
    ln_kernel<<<MROWS, 256>>>(nbuf, tmp, ln2_g, ln2_b, out);
}

// round 4
// speedup vs baseline: 1.7994x; 1.7994x over previous
#include <cuda_runtime.h>
#include <cuda_bf16.h>
#include <math.h>
#include <stdint.h>

// Problem constants
#define NX     768
#define NHEAD  12
#define DH     64
#define NCTX   2048
#define BATCH  4
#define MROWS  (BATCH * NCTX)        // 8192
#define EPS    1e-5f
#define NEGBIG -1000000000.0f

// ---------------- scratch (no allocations allowed) ----------------
__device__ float g_qkv [MROWS * 3 * NX];
__device__ float g_attn[MROWS * NX];
__device__ float g_n   [MROWS * NX];
__device__ float g_tmp [MROWS * NX];
__device__ __nv_bfloat16 g_ahi[MROWS * NX];
__device__ __nv_bfloat16 g_alo[MROWS * NX];
__device__ __nv_bfloat16 g_hhi[MROWS * 4 * NX];
__device__ __nv_bfloat16 g_hlo[MROWS * 4 * NX];
// transposed+split weights, packed: [w_attn^T | w_proj^T | w_fc^T | w_fc2^T]
#define WOFF_ATTN 0
#define WOFF_PROJ (3*NX*NX)
#define WOFF_FC   (WOFF_PROJ + NX*NX)
#define WOFF_FC2  (WOFF_FC + 4*NX*NX)
#define WTOTAL    (WOFF_FC2 + 4*NX*NX)
__device__ __nv_bfloat16 g_whi[WTOTAL];
__device__ __nv_bfloat16 g_wlo[WTOTAL];

// =====================================================================
// helpers
// =====================================================================
__device__ __forceinline__ uint32_t smem_u32(const void* p) {
    uint32_t a;
    asm("{ .reg .u64 t; cvta.to.shared.u64 t, %1; cvt.u32.u64 %0, t; }" : "=r"(a) : "l"(p));
    return a;
}
__device__ __forceinline__ void cp_async16(uint32_t s, const void* g) {
    asm volatile("cp.async.cg.shared.global [%0], [%1], 16;\n"
                 :: "r"(s), "l"(__cvta_generic_to_global(g)));
}
#define CP_COMMIT()   asm volatile("cp.async.commit_group;\n" ::: "memory")
#define CP_WAIT(n)    asm volatile("cp.async.wait_group %0;\n" :: "n"(n) : "memory")

__device__ __forceinline__ void ldsm_x4(uint32_t* r, uint32_t addr) {
    asm volatile("ldmatrix.sync.aligned.m8n8.x4.shared.b16 {%0,%1,%2,%3}, [%4];"
                 : "=r"(r[0]), "=r"(r[1]), "=r"(r[2]), "=r"(r[3]) : "r"(addr));
}
__device__ __forceinline__ void mma16816(float* d, const uint32_t* a, const uint32_t* b) {
    asm volatile(
        "mma.sync.aligned.m16n8k16.row.col.f32.bf16.bf16.f32 "
        "{%0,%1,%2,%3}, {%4,%5,%6,%7}, {%8,%9}, {%0,%1,%2,%3};"
        : "+f"(d[0]), "+f"(d[1]), "+f"(d[2]), "+f"(d[3])
        : "r"(a[0]), "r"(a[1]), "r"(a[2]), "r"(a[3]), "r"(b[0]), "r"(b[1]));
}

// =====================================================================
// HMMA split-bf16 GEMM: C[M,N] = (Ahi+Alo)[M,K] @ Wt[N,K]^T + bias
// D = Ahi*Whi + Alo*Whi + Ahi*Wlo   (fp32 accumulate)
// Tile 128x128x32, 256 threads (8 warps, 2Mx4N), double-buffered cp.async
// =====================================================================
#define ST     40                         // smem row stride in bf16 (80B)
#define TILEB  (128 * ST * 2)             // 10240B per tile
#define STAGEB (4 * TILEB)                // Ahi,Alo,Bhi,Blo = 40960B
#define GEMM_DSMEM (2 * STAGEB)           // 81920B

__global__ __launch_bounds__(256) void gemm_tc_kernel(
    const __nv_bfloat16* __restrict__ Ahi, const __nv_bfloat16* __restrict__ Alo,
    const __nv_bfloat16* __restrict__ Bhi, const __nv_bfloat16* __restrict__ Blo,
    const float* __restrict__ bias,
    float* __restrict__ C, __nv_bfloat16* __restrict__ Hhi, __nv_bfloat16* __restrict__ Hlo,
    int M, int N, int K, int relu)
{
    extern __shared__ __align__(16) char dsm[];
    const uint32_t sbase = smem_u32(dsm);

    const int tid  = threadIdx.x;
    const int wid  = tid >> 5;
    const int lane = tid & 31;
    const int wm   = wid >> 2;            // 0..1  (M)
    const int wn   = wid & 3;             // 0..3  (N)
    const int row0 = blockIdx.y * 128;
    const int col0 = blockIdx.x * 128;

    float acc[4][4][4];
#pragma unroll
    for (int mi = 0; mi < 4; mi++)
#pragma unroll
        for (int ni = 0; ni < 4; ni++)
#pragma unroll
            for (int j = 0; j < 4; j++) acc[mi][ni][j] = 0.0f;

    const int nchunks = K >> 5;

    // stage tile loader: 128 rows x 32 k, 4x16B chunks per row
    auto load_stage = [&](int i) {
        const uint32_t st = sbase + (i & 1) * STAGEB;
        const int kt = i << 5;
#pragma unroll 2
        for (int u = tid; u < 512; u += 256) {
            int r = u >> 2, c = u & 3;
            uint32_t off = (uint32_t)(r * (ST * 2) + c * 16);
            size_t ga = (size_t)(row0 + r) * K + kt + c * 8;
            size_t gb = (size_t)(col0 + r) * K + kt + c * 8;
            cp_async16(st + off,              Ahi + ga);
            cp_async16(st + TILEB + off,      Alo + ga);
            cp_async16(st + 2 * TILEB + off,  Bhi + gb);
            cp_async16(st + 3 * TILEB + off,  Blo + gb);
        }
        CP_COMMIT();
    };

    load_stage(0);

    // ldmatrix lane addressing (element offsets precomputed)
    const int lr = lane & 7;
    const int lg = lane >> 3;             // group 0..3
    // A: groups (m0k0),(m8k0),(m0k8),(m8k8)
    const int a_row = lr + (lg & 1) * 8;
    const int a_col = (lg >> 1) * 8;
    // B: groups (n0k0),(n0k8),(n8k0),(n8k8)  -> regs {b01,b23} per n-frag pair
    const int b_rowg = (lg >> 1) * 8 + lr;
    const int b_colg = (lg & 1) * 8;

    for (int i = 0; i < nchunks; i++) {
        if (i + 1 < nchunks) { load_stage(i + 1); CP_WAIT(1); }
        else                 { CP_WAIT(0); }
        __syncthreads();

        const uint32_t st  = sbase + (i & 1) * STAGEB;
        const uint32_t sAh = st;
        const uint32_t sAl = st + TILEB;
        const uint32_t sBh = st + 2 * TILEB;
        const uint32_t sBl = st + 3 * TILEB;

#pragma unroll
        for (int ks = 0; ks < 2; ks++) {
            const int kc = ks * 16;
            uint32_t bhi[4][2], blo[4][2];
#pragma unroll
            for (int p = 0; p < 2; p++) {
                int nrow = wn * 32 + p * 16 + b_rowg;
                uint32_t off = (uint32_t)(nrow * (ST * 2) + (kc + b_colg) * 2);
                uint32_t r4[4];
                ldsm_x4(r4, sBh + off);
                bhi[p*2][0] = r4[0]; bhi[p*2][1] = r4[1];
                bhi[p*2+1][0] = r4[2]; bhi[p*2+1][1] = r4[3];
                ldsm_x4(r4, sBl + off);
                blo[p*2][0] = r4[0]; blo[p*2][1] = r4[1];
                blo[p*2+1][0] = r4[2]; blo[p*2+1][1] = r4[3];
            }
#pragma unroll
            for (int mi = 0; mi < 4; mi++) {
                int mrow = wm * 64 + mi * 16 + a_row;
                uint32_t off = (uint32_t)(mrow * (ST * 2) + (kc + a_col) * 2);
                uint32_t ah[4], al[4];
                ldsm_x4(ah, sAh + off);
                ldsm_x4(al, sAl + off);
#pragma unroll
                for (int ni = 0; ni < 4; ni++) {
                    mma16816(acc[mi][ni], ah, bhi[ni]);
                    mma16816(acc[mi][ni], al, bhi[ni]);
                    mma16816(acc[mi][ni], ah, blo[ni]);
                }
            }
        }
        __syncthreads();
    }

    // ---------------- epilogue: regs -> smem (132-stride) -> gmem ----------------
    float* sof = (float*)dsm;
    const int qr = lane >> 2;
    const int qc = (lane & 3) * 2;
#pragma unroll
    for (int mi = 0; mi < 4; mi++) {
#pragma unroll
        for (int ni = 0; ni < 4; ni++) {
            int r = wm * 64 + mi * 16 + qr;
            int c = wn * 32 + ni * 8 + qc;
            *(float2*)(sof + r * 132 + c)       = make_float2(acc[mi][ni][0], acc[mi][ni][1]);
            *(float2*)(sof + (r + 8) * 132 + c) = make_float2(acc[mi][ni][2], acc[mi][ni][3]);
        }
    }
    __syncthreads();

    for (int i = tid; i < 128 * 32; i += 256) {
        int r = i >> 5, cu = i & 31;
        float4 v = *(float4*)(sof + r * 132 + cu * 4);
        int gcol = col0 + cu * 4;
        float4 bb = *(const float4*)(bias + gcol);
        v.x += bb.x; v.y += bb.y; v.z += bb.z; v.w += bb.w;
        if (relu) {
            v.x = fmaxf(v.x, 0.0f); v.y = fmaxf(v.y, 0.0f);
            v.z = fmaxf(v.z, 0.0f); v.w = fmaxf(v.w, 0.0f);
        }
        size_t gi = (size_t)(row0 + r) * N + gcol;
        if (C) *(float4*)(C + gi) = v;
        if (Hhi) {
            __nv_bfloat16 h0 = __float2bfloat16(v.x), h1 = __float2bfloat16(v.y);
            __nv_bfloat16 h2 = __float2bfloat16(v.z), h3 = __float2bfloat16(v.w);
            __nv_bfloat162 p0; p0.x = h0; p0.y = h1;
            __nv_bfloat162 p1; p1.x = h2; p1.y = h3;
            *(__nv_bfloat162*)(Hhi + gi) = p0;
            *(__nv_bfloat162*)(Hhi + gi + 2) = p1;
            __nv_bfloat162 q0, q1;
            q0.x = __float2bfloat16(v.x - __bfloat162float(h0));
            q0.y = __float2bfloat16(v.y - __bfloat162float(h1));
            q1.x = __float2bfloat16(v.z - __bfloat162float(h2));
            q1.y = __float2bfloat16(v.w - __bfloat162float(h3));
            *(__nv_bfloat162*)(Hlo + gi) = q0;
            *(__nv_bfloat162*)(Hlo + gi + 2) = q1;
        }
    }
}

// =====================================================================
// weight transpose + bf16 split: Wt[n][k] = split(W[k][n])
// =====================================================================
__global__ __launch_bounds__(256) void tsplit_kernel(
    const float* __restrict__ W, __nv_bfloat16* __restrict__ hi,
    __nv_bfloat16* __restrict__ lo, int K, int N)
{
    __shared__ float t[32][33];
    const int n0 = blockIdx.x * 32, k0 = blockIdx.y * 32;
    const int tx = threadIdx.x & 31, ty = threadIdx.x >> 5;
#pragma unroll
    for (int i = 0; i < 32; i += 8)
        t[ty + i][tx] = W[(size_t)(k0 + ty + i) * N + n0 + tx];
    __syncthreads();
#pragma unroll
    for (int i = 0; i < 32; i += 8) {
        float v = t[tx][ty + i];
        __nv_bfloat16 h = __float2bfloat16(v);
        size_t o = (size_t)(n0 + ty + i) * K + k0 + tx;
        hi[o] = h;
        lo[o] = __float2bfloat16(v - __bfloat162float(h));
    }
}

// elementwise bf16 split
__global__ __launch_bounds__(256) void split_kernel(
    const float* __restrict__ in, __nv_bfloat16* __restrict__ hi,
    __nv_bfloat16* __restrict__ lo, int n4)
{
    int i = blockIdx.x * blockDim.x + threadIdx.x;
    if (i >= n4) return;
    float4 v = *(const float4*)(in + i * 4);
    __nv_bfloat16 h0 = __float2bfloat16(v.x), h1 = __float2bfloat16(v.y);
    __nv_bfloat16 h2 = __float2bfloat16(v.z), h3 = __float2bfloat16(v.w);
    __nv_bfloat162 p0; p0.x = h0; p0.y = h1;
    __nv_bfloat162 p1; p1.x = h2; p1.y = h3;
    *(__nv_bfloat162*)(hi + i * 4) = p0;
    *(__nv_bfloat162*)(hi + i * 4 + 2) = p1;
    __nv_bfloat162 q0, q1;
    q0.x = __float2bfloat16(v.x - __bfloat162float(h0));
    q0.y = __float2bfloat16(v.y - __bfloat162float(h1));
    q1.x = __float2bfloat16(v.z - __bfloat162float(h2));
    q1.y = __float2bfloat16(v.w - __bfloat162float(h3));
    *(__nv_bfloat162*)(lo + i * 4) = q0;
    *(__nv_bfloat162*)(lo + i * 4 + 2) = q1;
}

// =====================================================================
// Flash attention (causal, NO 1/sqrt(d) scale)
// =====================================================================
__global__ __launch_bounds__(256) void attn_kernel(
    const float* __restrict__ qkv, float* __restrict__ out)
{
    __shared__ float Qs[64][65];
    __shared__ float Ks[32][65];
    __shared__ float Vs[32][65];
    __shared__ float Ps[64][33];

    const int tid = threadIdx.x;
    const int tx = tid & 15;
    const int ty = tid >> 4;
    const int it = blockIdx.x;
    const int h  = blockIdx.y;
    const int b  = blockIdx.z;
    const int brow = b * NCTX + it * 64;

    for (int idx = tid; idx < 64 * 64; idx += 256) {
        int r = idx >> 6, d = idx & 63;
        Qs[r][d] = qkv[(size_t)(brow + r) * (3 * NX) + h * DH + d];
    }

    float o[4][4];
    float m[4], l[4];
#pragma unroll
    for (int i = 0; i < 4; i++) {
        m[i] = -INFINITY; l[i] = 0.0f;
#pragma unroll
        for (int j = 0; j < 4; j++) o[i][j] = 0.0f;
    }

    const int jmax = 2 * it + 1;
    for (int jt = 0; jt <= jmax; jt++) {
        for (int idx = tid; idx < 32 * 64; idx += 256) {
            int r = idx >> 6, d = idx & 63;
            size_t base = (size_t)(b * NCTX + jt * 32 + r) * (3 * NX) + h * DH + d;
            Ks[r][d] = qkv[base + NX];
            Vs[r][d] = qkv[base + 2 * NX];
        }
        __syncthreads();

        float s[4][2];
#pragma unroll
        for (int i = 0; i < 4; i++) { s[i][0] = 0.0f; s[i][1] = 0.0f; }
#pragma unroll 8
        for (int d = 0; d < 64; d++) {
            float q0 = Qs[ty * 4 + 0][d];
            float q1 = Qs[ty * 4 + 1][d];
            float q2 = Qs[ty * 4 + 2][d];
            float q3 = Qs[ty * 4 + 3][d];
            float k0 = Ks[tx * 2 + 0][d];
            float k1 = Ks[tx * 2 + 1][d];
            s[0][0] = fmaf(q0, k0, s[0][0]); s[0][1] = fmaf(q0, k1, s[0][1]);
            s[1][0] = fmaf(q1, k0, s[1][0]); s[1][1] = fmaf(q1, k1, s[1][1]);
            s[2][0] = fmaf(q2, k0, s[2][0]); s[2][1] = fmaf(q2, k1, s[2][1]);
            s[3][0] = fmaf(q3, k0, s[3][0]); s[3][1] = fmaf(q3, k1, s[3][1]);
        }

        if (jt >= 2 * it) {
#pragma unroll
            for (int i = 0; i < 4; i++) {
                int gr = it * 64 + ty * 4 + i;
#pragma unroll
                for (int j = 0; j < 2; j++) {
                    int gc = jt * 32 + tx * 2 + j;
                    if (gc > gr) s[i][j] = NEGBIG;
                }
            }
        }

        float alpha[4];
#pragma unroll
        for (int i = 0; i < 4; i++) {
            float mt = fmaxf(s[i][0], s[i][1]);
#pragma unroll
            for (int off = 8; off > 0; off >>= 1)
                mt = fmaxf(mt, __shfl_xor_sync(0xffffffffu, mt, off));
            float mnew = fmaxf(m[i], mt);
            alpha[i] = __expf(m[i] - mnew);
            float p0 = __expf(s[i][0] - mnew);
            float p1 = __expf(s[i][1] - mnew);
            float ps = p0 + p1;
#pragma unroll
            for (int off = 8; off > 0; off >>= 1)
                ps += __shfl_xor_sync(0xffffffffu, ps, off);
            l[i] = l[i] * alpha[i] + ps;
            m[i] = mnew;
            Ps[ty * 4 + i][tx * 2 + 0] = p0;
            Ps[ty * 4 + i][tx * 2 + 1] = p1;
#pragma unroll
            for (int j = 0; j < 4; j++) o[i][j] *= alpha[i];
        }
        __syncthreads();

#pragma unroll 8
        for (int c = 0; c < 32; c++) {
            float v0 = Vs[c][tx * 4 + 0];
            float v1 = Vs[c][tx * 4 + 1];
            float v2 = Vs[c][tx * 4 + 2];
            float v3 = Vs[c][tx * 4 + 3];
#pragma unroll
            for (int i = 0; i < 4; i++) {
                float p = Ps[ty * 4 + i][c];
                o[i][0] = fmaf(p, v0, o[i][0]);
                o[i][1] = fmaf(p, v1, o[i][1]);
                o[i][2] = fmaf(p, v2, o[i][2]);
                o[i][3] = fmaf(p, v3, o[i][3]);
            }
        }
        __syncthreads();
    }

#pragma unroll
    for (int i = 0; i < 4; i++) {
        float inv = 1.0f / l[i];
        float* op = out + (size_t)(brow + ty * 4 + i) * NX + h * DH + tx * 4;
#pragma unroll
        for (int j = 0; j < 4; j++) op[j] = o[i][j] * inv;
    }
}

// =====================================================================
// LayerNorm (additive, faithful to source bug) + optional bf16 split out
// =====================================================================
__global__ __launch_bounds__(256) void ln_kernel(
    const float* __restrict__ in1, const float* __restrict__ in2,
    const float* __restrict__ g, const float* __restrict__ bb,
    float* __restrict__ out, __nv_bfloat16* __restrict__ ohi,
    __nv_bfloat16* __restrict__ olo)
{
    __shared__ float buf[NX];
    __shared__ float red[256];
    __shared__ float red2[256];

    const int row = blockIdx.x;
    const int tid = threadIdx.x;
    const size_t base = (size_t)row * NX;

    float s = 0.0f, s2 = 0.0f;
#pragma unroll
    for (int k = 0; k < 3; k++) {
        int i = tid + k * 256;
        float v = in1[base + i] + in2[base + i];
        buf[i] = v;
        s += v; s2 += v * v;
    }
    red[tid] = s; red2[tid] = s2;
    __syncthreads();
    for (int off = 128; off > 0; off >>= 1) {
        if (tid < off) { red[tid] += red[tid + off]; red2[tid] += red2[tid + off]; }
        __syncthreads();
    }
    const float u = red[0] * (1.0f / NX);
    const float var = red2[0] * (1.0f / NX) - u * u;
    const float rstd = rsqrtf(var + EPS);
#pragma unroll
    for (int k = 0; k < 3; k++) {
        int i = tid + k * 256;
        float v = g[i] + (buf[i] - u) * rstd + bb[i];
        out[base + i] = v;
        if (ohi) {
            __nv_bfloat16 h = __float2bfloat16(v);
            ohi[base + i] = h;
            olo[base + i] = __float2bfloat16(v - __bfloat162float(h));
        }
    }
}

// =====================================================================
extern "C" void kernel_launch(void* const* d_in, const int* in_sizes, int n_in,
                              void* d_out, int out_size)
{
    const float* x      = (const float*)d_in[0];
    const float* w_attn = (const float*)d_in[1];
    const float* b_attn = (const float*)d_in[2];
    const float* w_proj = (const float*)d_in[3];
    const float* b_proj = (const float*)d_in[4];
    const float* ln1_g  = (const float*)d_in[5];
    const float* ln1_b  = (const float*)d_in[6];
    const float* w_fc   = (const float*)d_in[7];
    const float* b_fc   = (const float*)d_in[8];
    const float* w_fc2  = (const float*)d_in[9];
    const float* b_fc2  = (const float*)d_in[10];
    const float* ln2_g  = (const float*)d_in[11];
    const float* ln2_b  = (const float*)d_in[12];
    float* out = (float*)d_out;

    float *qkv, *attn, *nbuf, *tmp;
    __nv_bfloat16 *ahi, *alo, *hhi, *hlo, *whi, *wlo;
    cudaGetSymbolAddress((void**)&qkv,  g_qkv);
    cudaGetSymbolAddress((void**)&attn, g_attn);
    cudaGetSymbolAddress((void**)&nbuf, g_n);
    cudaGetSymbolAddress((void**)&tmp,  g_tmp);
    cudaGetSymbolAddress((void**)&ahi,  g_ahi);
    cudaGetSymbolAddress((void**)&alo,  g_alo);
    cudaGetSymbolAddress((void**)&hhi,  g_hhi);
    cudaGetSymbolAddress((void**)&hlo,  g_hlo);
    cudaGetSymbolAddress((void**)&whi,  g_whi);
    cudaGetSymbolAddress((void**)&wlo,  g_wlo);

    static int smem_set = 0;
    if (!smem_set) {
        cudaFuncSetAttribute(gemm_tc_kernel,
                             cudaFuncAttributeMaxDynamicSharedMemorySize, GEMM_DSMEM);
        smem_set = 1;
    }

    // --- weight prep: transpose + bf16 split ---
    tsplit_kernel<<<dim3(3 * NX / 32, NX / 32), 256>>>(w_attn, whi + WOFF_ATTN, wlo + WOFF_ATTN, NX, 3 * NX);
    tsplit_kernel<<<dim3(NX / 32, NX / 32),     256>>>(w_proj, whi + WOFF_PROJ, wlo + WOFF_PROJ, NX, NX);
    tsplit_kernel<<<dim3(4 * NX / 32, NX / 32), 256>>>(w_fc,   whi + WOFF_FC,   wlo + WOFF_FC,   NX, 4 * NX);
    tsplit_kernel<<<dim3(NX / 32, 4 * NX / 32), 256>>>(w_fc2,  whi + WOFF_FC2,  wlo + WOFF_FC2,  4 * NX, NX);

    // --- x split ---
    split_kernel<<<(MROWS * NX / 4 + 255) / 256, 256>>>(x, ahi, alo, MROWS * NX / 4);

    // 1. qkv = x @ w_attn + b_attn
    gemm_tc_kernel<<<dim3(3 * NX / 128, MROWS / 128), 256, GEMM_DSMEM>>>(
        ahi, alo, whi + WOFF_ATTN, wlo + WOFF_ATTN, b_attn, qkv, nullptr, nullptr,
        MROWS, 3 * NX, NX, 0);

    // 2. attention
    attn_kernel<<<dim3(NCTX / 64, NHEAD, BATCH), 256>>>(qkv, attn);

    // 3. proj = attn @ w_proj + b_proj
    split_kernel<<<(MROWS * NX / 4 + 255) / 256, 256>>>(attn, ahi, alo, MROWS * NX / 4);
    gemm_tc_kernel<<<dim3(NX / 128, MROWS / 128), 256, GEMM_DSMEM>>>(
        ahi, alo, whi + WOFF_PROJ, wlo + WOFF_PROJ, b_proj, tmp, nullptr, nullptr,
        MROWS, NX, NX, 0);

    // 4. n = LN(x + proj)  (+ split for fc)
    ln_kernel<<<MROWS, 256>>>(x, tmp, ln1_g, ln1_b, nbuf, ahi, alo);

    // 5. h = relu(n @ w_fc + b_fc)  -> bf16 hi/lo only
    gemm_tc_kernel<<<dim3(4 * NX / 128, MROWS / 128), 256, GEMM_DSMEM>>>(
        ahi, alo, whi + WOFF_FC, wlo + WOFF_FC, b_fc, nullptr, hhi, hlo,
        MROWS, 4 * NX, NX, 1);

    // 6. m = h @ w_fc2 + b_fc2
    gemm_tc_kernel<<<dim3(NX / 128, MROWS / 128), 256, GEMM_DSMEM>>>(
        hhi, hlo, whi + WOFF_FC2, wlo + WOFF_FC2, b_fc2, tmp, nullptr, nullptr,
        MROWS, NX, 4 * NX, 0);

    // 7. out = LN(n + m)
    ln_kernel<<<MROWS, 256>>>(nbuf, tmp, ln2_g, ln2_b, out, nullptr, nullptr);
}

// round 5
// speedup vs baseline: 2.8027x; 1.5576x over previous
#include <cuda_runtime.h>
#include <cuda_bf16.h>
#include <math.h>
#include <stdint.h>

// Problem constants
#define NX     768
#define NHEAD  12
#define DH     64
#define NCTX   2048
#define BATCH  4
#define MROWS  (BATCH * NCTX)        // 8192
#define EPS    1e-5f
#define NEGBIG -1000000000.0f

// ---------------- scratch (no allocations allowed) ----------------
__device__ float g_n   [MROWS * NX];
__device__ float g_tmp [MROWS * NX];
__device__ __nv_bfloat16 g_ahi[MROWS * NX];
__device__ __nv_bfloat16 g_alo[MROWS * NX];
__device__ __nv_bfloat16 g_hhi[MROWS * 4 * NX];   // also holds qkv split (2304<=3072)
__device__ __nv_bfloat16 g_hlo[MROWS * 4 * NX];
#define WOFF_ATTN 0
#define WOFF_PROJ (3*NX*NX)
#define WOFF_FC   (WOFF_PROJ + NX*NX)
#define WOFF_FC2  (WOFF_FC + 4*NX*NX)
#define WTOTAL    (WOFF_FC2 + 4*NX*NX)
__device__ __nv_bfloat16 g_whi[WTOTAL];
__device__ __nv_bfloat16 g_wlo[WTOTAL];

// =====================================================================
// helpers
// =====================================================================
__device__ __forceinline__ uint32_t smem_u32(const void* p) {
    uint32_t a;
    asm("{ .reg .u64 t; cvta.to.shared.u64 t, %1; cvt.u32.u64 %0, t; }" : "=r"(a) : "l"(p));
    return a;
}
__device__ __forceinline__ void cp_async16(uint32_t s, const void* g) {
    asm volatile("cp.async.cg.shared.global [%0], [%1], 16;\n"
                 :: "r"(s), "l"(__cvta_generic_to_global(g)));
}
#define CP_COMMIT()   asm volatile("cp.async.commit_group;\n" ::: "memory")
#define CP_WAIT(n)    asm volatile("cp.async.wait_group %0;\n" :: "n"(n) : "memory")

__device__ __forceinline__ void ldsm_x4(uint32_t* r, uint32_t addr) {
    asm volatile("ldmatrix.sync.aligned.m8n8.x4.shared.b16 {%0,%1,%2,%3}, [%4];"
                 : "=r"(r[0]), "=r"(r[1]), "=r"(r[2]), "=r"(r[3]) : "r"(addr));
}
__device__ __forceinline__ void ldsm_x4_t(uint32_t* r, uint32_t addr) {
    asm volatile("ldmatrix.sync.aligned.m8n8.x4.trans.shared.b16 {%0,%1,%2,%3}, [%4];"
                 : "=r"(r[0]), "=r"(r[1]), "=r"(r[2]), "=r"(r[3]) : "r"(addr));
}
__device__ __forceinline__ void mma16816(float* d, const uint32_t* a, const uint32_t* b) {
    asm volatile(
        "mma.sync.aligned.m16n8k16.row.col.f32.bf16.bf16.f32 "
        "{%0,%1,%2,%3}, {%4,%5,%6,%7}, {%8,%9}, {%0,%1,%2,%3};"
        : "+f"(d[0]), "+f"(d[1]), "+f"(d[2]), "+f"(d[3])
        : "r"(a[0]), "r"(a[1]), "r"(a[2]), "r"(a[3]), "r"(b[0]), "r"(b[1]));
}
__device__ __forceinline__ uint32_t pack_bf16(float lo, float hi) {
    __nv_bfloat162 t = __floats2bfloat162_rn(lo, hi);
    return *reinterpret_cast<uint32_t*>(&t);
}

// =====================================================================
// HMMA split-bf16 GEMM (unchanged from R4, passing)
// =====================================================================
#define ST     40
#define TILEB  (128 * ST * 2)
#define STAGEB (4 * TILEB)
#define GEMM_DSMEM (2 * STAGEB)

__global__ __launch_bounds__(256) void gemm_tc_kernel(
    const __nv_bfloat16* __restrict__ Ahi, const __nv_bfloat16* __restrict__ Alo,
    const __nv_bfloat16* __restrict__ Bhi, const __nv_bfloat16* __restrict__ Blo,
    const float* __restrict__ bias,
    float* __restrict__ C, __nv_bfloat16* __restrict__ Hhi, __nv_bfloat16* __restrict__ Hlo,
    int M, int N, int K, int relu)
{
    extern __shared__ __align__(16) char dsm[];
    const uint32_t sbase = smem_u32(dsm);

    const int tid  = threadIdx.x;
    const int wid  = tid >> 5;
    const int lane = tid & 31;
    const int wm   = wid >> 2;
    const int wn   = wid & 3;
    const int row0 = blockIdx.y * 128;
    const int col0 = blockIdx.x * 128;

    float acc[4][4][4];
#pragma unroll
    for (int mi = 0; mi < 4; mi++)
#pragma unroll
        for (int ni = 0; ni < 4; ni++)
#pragma unroll
            for (int j = 0; j < 4; j++) acc[mi][ni][j] = 0.0f;

    const int nchunks = K >> 5;

    auto load_stage = [&](int i) {
        const uint32_t st = sbase + (i & 1) * STAGEB;
        const int kt = i << 5;
#pragma unroll 2
        for (int u = tid; u < 512; u += 256) {
            int r = u >> 2, c = u & 3;
            uint32_t off = (uint32_t)(r * (ST * 2) + c * 16);
            size_t ga = (size_t)(row0 + r) * K + kt + c * 8;
            size_t gb = (size_t)(col0 + r) * K + kt + c * 8;
            cp_async16(st + off,              Ahi + ga);
            cp_async16(st + TILEB + off,      Alo + ga);
            cp_async16(st + 2 * TILEB + off,  Bhi + gb);
            cp_async16(st + 3 * TILEB + off,  Blo + gb);
        }
        CP_COMMIT();
    };

    load_stage(0);

    const int lr8 = lane & 7;
    const int lg  = lane >> 3;
    const int a_row = lr8 + (lg & 1) * 8;
    const int a_col = (lg >> 1) * 8;
    const int b_rowg = (lg >> 1) * 8 + lr8;
    const int b_colg = (lg & 1) * 8;

    for (int i = 0; i < nchunks; i++) {
        if (i + 1 < nchunks) { load_stage(i + 1); CP_WAIT(1); }
        else                 { CP_WAIT(0); }
        __syncthreads();

        const uint32_t st  = sbase + (i & 1) * STAGEB;
        const uint32_t sAh = st;
        const uint32_t sAl = st + TILEB;
        const uint32_t sBh = st + 2 * TILEB;
        const uint32_t sBl = st + 3 * TILEB;

#pragma unroll
        for (int ks = 0; ks < 2; ks++) {
            const int kc = ks * 16;
            uint32_t bhi[4][2], blo[4][2];
#pragma unroll
            for (int p = 0; p < 2; p++) {
                int nrow = wn * 32 + p * 16 + b_rowg;
                uint32_t off = (uint32_t)(nrow * (ST * 2) + (kc + b_colg) * 2);
                uint32_t r4[4];
                ldsm_x4(r4, sBh + off);
                bhi[p*2][0] = r4[0]; bhi[p*2][1] = r4[1];
                bhi[p*2+1][0] = r4[2]; bhi[p*2+1][1] = r4[3];
                ldsm_x4(r4, sBl + off);
                blo[p*2][0] = r4[0]; blo[p*2][1] = r4[1];
                blo[p*2+1][0] = r4[2]; blo[p*2+1][1] = r4[3];
            }
#pragma unroll
            for (int mi = 0; mi < 4; mi++) {
                int mrow = wm * 64 + mi * 16 + a_row;
                uint32_t off = (uint32_t)(mrow * (ST * 2) + (kc + a_col) * 2);
                uint32_t ah[4], al[4];
                ldsm_x4(ah, sAh + off);
                ldsm_x4(al, sAl + off);
#pragma unroll
                for (int ni = 0; ni < 4; ni++) {
                    mma16816(acc[mi][ni], ah, bhi[ni]);
                    mma16816(acc[mi][ni], al, bhi[ni]);
                    mma16816(acc[mi][ni], ah, blo[ni]);
                }
            }
        }
        __syncthreads();
    }

    float* sof = (float*)dsm;
    const int qr = lane >> 2;
    const int qc2 = (lane & 3) * 2;
#pragma unroll
    for (int mi = 0; mi < 4; mi++) {
#pragma unroll
        for (int ni = 0; ni < 4; ni++) {
            int r = wm * 64 + mi * 16 + qr;
            int c = wn * 32 + ni * 8 + qc2;
            *(float2*)(sof + r * 132 + c)       = make_float2(acc[mi][ni][0], acc[mi][ni][1]);
            *(float2*)(sof + (r + 8) * 132 + c) = make_float2(acc[mi][ni][2], acc[mi][ni][3]);
        }
    }
    __syncthreads();

    for (int i = tid; i < 128 * 32; i += 256) {
        int r = i >> 5, cu = i & 31;
        float4 v = *(float4*)(sof + r * 132 + cu * 4);
        int gcol = col0 + cu * 4;
        float4 bb = *(const float4*)(bias + gcol);
        v.x += bb.x; v.y += bb.y; v.z += bb.z; v.w += bb.w;
        if (relu) {
            v.x = fmaxf(v.x, 0.0f); v.y = fmaxf(v.y, 0.0f);
            v.z = fmaxf(v.z, 0.0f); v.w = fmaxf(v.w, 0.0f);
        }
        size_t gi = (size_t)(row0 + r) * N + gcol;
        if (C) *(float4*)(C + gi) = v;
        if (Hhi) {
            __nv_bfloat16 h0 = __float2bfloat16(v.x), h1 = __float2bfloat16(v.y);
            __nv_bfloat16 h2 = __float2bfloat16(v.z), h3 = __float2bfloat16(v.w);
            __nv_bfloat162 p0; p0.x = h0; p0.y = h1;
            __nv_bfloat162 p1; p1.x = h2; p1.y = h3;
            *(__nv_bfloat162*)(Hhi + gi) = p0;
            *(__nv_bfloat162*)(Hhi + gi + 2) = p1;
            __nv_bfloat162 q0, q1;
            q0.x = __float2bfloat16(v.x - __bfloat162float(h0));
            q0.y = __float2bfloat16(v.y - __bfloat162float(h1));
            q1.x = __float2bfloat16(v.z - __bfloat162float(h2));
            q1.y = __float2bfloat16(v.w - __bfloat162float(h3));
            *(__nv_bfloat162*)(Hlo + gi) = q0;
            *(__nv_bfloat162*)(Hlo + gi + 2) = q1;
        }
    }
}

// =====================================================================
// HMMA flash attention (causal, NO scale), split-bf16 numerics.
// Input: qkv split hi/lo [8192][2304]. Output: attn split hi/lo [8192][768].
// CTA: 128 Q rows (8 warps x 16), iterate K/V in 64-chunks.
// =====================================================================
#define AST    72                              // smem row stride (bf16), 144B
#define A_Q_BYTES (128 * AST * 2)              // 18432
#define A_KV_BYTES (64 * AST * 2)              // 9216
#define SQH 0
#define SQL (A_Q_BYTES)
#define SKH (2 * A_Q_BYTES)
#define SKL (2 * A_Q_BYTES + A_KV_BYTES)
#define SVH (2 * A_Q_BYTES + 2 * A_KV_BYTES)
#define SVL (2 * A_Q_BYTES + 3 * A_KV_BYTES)
#define ATTN_DSMEM (2 * A_Q_BYTES + 4 * A_KV_BYTES)   // 73728

__global__ __launch_bounds__(256) void attn_mma_kernel(
    const __nv_bfloat16* __restrict__ qh_, const __nv_bfloat16* __restrict__ ql_,
    __nv_bfloat16* __restrict__ ohi_, __nv_bfloat16* __restrict__ olo_)
{
    extern __shared__ __align__(16) char dsm[];
    const uint32_t sb = smem_u32(dsm);

    const int tid  = threadIdx.x;
    const int wid  = tid >> 5;
    const int lane = tid & 31;
    const int it = blockIdx.x;
    const int h  = blockIdx.y;
    const int b  = blockIdx.z;
    const int row0  = it * 128;                 // seq-local
    const int grow0 = b * NCTX + row0;

    // load Q tile (128 x 64) hi+lo
    for (int u = tid; u < 1024; u += 256) {
        int r = u >> 3, c = u & 7;
        uint32_t off = (uint32_t)(r * (AST * 2) + c * 16);
        size_t gi = (size_t)(grow0 + r) * (3 * NX) + h * DH + c * 8;
        cp_async16(sb + SQH + off, qh_ + gi);
        cp_async16(sb + SQL + off, ql_ + gi);
    }
    CP_COMMIT();

    const int wr  = wid * 16;
    const int lr  = lane >> 2;                  // quad row
    const int qc  = lane & 3;
    const int lr8 = lane & 7;
    const int lg  = lane >> 3;
    const int a_row = lr8 + (lg & 1) * 8;
    const int a_col = (lg >> 1) * 8;
    const int b_rowg = (lg >> 1) * 8 + lr8;
    const int b_colg = (lg & 1) * 8;
    const int v_row = (lg & 1) * 8 + lr8;       // trans-ldmatrix (V^T)
    const int v_col = (lg >> 1) * 8;

    CP_WAIT(0);
    __syncthreads();

    // Q fragments, register-resident
    uint32_t qh[4][4], ql[4][4];
#pragma unroll
    for (int kk = 0; kk < 4; kk++) {
        uint32_t off = (uint32_t)((wr + a_row) * (AST * 2) + (kk * 16 + a_col) * 2);
        ldsm_x4(qh[kk], sb + SQH + off);
        ldsm_x4(ql[kk], sb + SQL + off);
    }

    float m0 = -INFINITY, m1 = -INFINITY, l0 = 0.0f, l1 = 0.0f;
    float o[8][4];
#pragma unroll
    for (int ni = 0; ni < 8; ni++)
#pragma unroll
        for (int e = 0; e < 4; e++) o[ni][e] = 0.0f;

    const int jmax = 2 * it + 1;
    for (int jt = 0; jt <= jmax; jt++) {
        // load K,V tiles (64 x 64) hi+lo
        for (int u = tid; u < 512; u += 256) {
            int r = u >> 3, c = u & 7;
            uint32_t off = (uint32_t)(r * (AST * 2) + c * 16);
            size_t gk = (size_t)(b * NCTX + jt * 64 + r) * (3 * NX) + NX + h * DH + c * 8;
            cp_async16(sb + SKH + off, qh_ + gk);
            cp_async16(sb + SKL + off, ql_ + gk);
            cp_async16(sb + SVH + off, qh_ + gk + NX);
            cp_async16(sb + SVL + off, ql_ + gk + NX);
        }
        CP_COMMIT(); CP_WAIT(0);
        __syncthreads();

        const int col0 = jt * 64;
        const bool fullmask = col0 > row0 + wr + 15;
        if (!fullmask) {
            // ---- S = Q K^T (3-term split) ----
            float s[8][4];
#pragma unroll
            for (int ni = 0; ni < 8; ni++)
#pragma unroll
                for (int e = 0; e < 4; e++) s[ni][e] = 0.0f;

#pragma unroll
            for (int kk = 0; kk < 4; kk++) {
                uint32_t bh[8][2], bl[8][2];
#pragma unroll
                for (int p = 0; p < 4; p++) {
                    uint32_t off = (uint32_t)((p * 16 + b_rowg) * (AST * 2) + (kk * 16 + b_colg) * 2);
                    uint32_t r4[4];
                    ldsm_x4(r4, sb + SKH + off);
                    bh[p*2][0] = r4[0]; bh[p*2][1] = r4[1];
                    bh[p*2+1][0] = r4[2]; bh[p*2+1][1] = r4[3];
                    ldsm_x4(r4, sb + SKL + off);
                    bl[p*2][0] = r4[0]; bl[p*2][1] = r4[1];
                    bl[p*2+1][0] = r4[2]; bl[p*2+1][1] = r4[3];
                }
#pragma unroll
                for (int ni = 0; ni < 8; ni++) {
                    mma16816(s[ni], qh[kk], bh[ni]);
                    mma16816(s[ni], ql[kk], bh[ni]);
                    mma16816(s[ni], qh[kk], bl[ni]);
                }
            }

            // ---- causal mask (tiles crossing the diagonal) ----
            if (col0 + 63 > row0 + wr) {
                const int gr0 = row0 + wr + lr;
#pragma unroll
                for (int ni = 0; ni < 8; ni++) {
                    int gc = col0 + ni * 8 + qc * 2;
                    if (gc > gr0)         s[ni][0] = NEGBIG;
                    if (gc + 1 > gr0)     s[ni][1] = NEGBIG;
                    if (gc > gr0 + 8)     s[ni][2] = NEGBIG;
                    if (gc + 1 > gr0 + 8) s[ni][3] = NEGBIG;
                }
            }

            // ---- online softmax (rows lr and lr+8) ----
            float mt0 = s[0][0], mt1 = s[0][2];
#pragma unroll
            for (int ni = 0; ni < 8; ni++) {
                mt0 = fmaxf(mt0, fmaxf(s[ni][0], s[ni][1]));
                mt1 = fmaxf(mt1, fmaxf(s[ni][2], s[ni][3]));
            }
            mt0 = fmaxf(mt0, __shfl_xor_sync(0xffffffffu, mt0, 1));
            mt0 = fmaxf(mt0, __shfl_xor_sync(0xffffffffu, mt0, 2));
            mt1 = fmaxf(mt1, __shfl_xor_sync(0xffffffffu, mt1, 1));
            mt1 = fmaxf(mt1, __shfl_xor_sync(0xffffffffu, mt1, 2));
            float mn0 = fmaxf(m0, mt0), mn1 = fmaxf(m1, mt1);
            float al0 = __expf(m0 - mn0), al1 = __expf(m1 - mn1);
            m0 = mn0; m1 = mn1;

            float sum0 = 0.0f, sum1 = 0.0f;
#pragma unroll
            for (int ni = 0; ni < 8; ni++) {
                s[ni][0] = __expf(s[ni][0] - mn0);
                s[ni][1] = __expf(s[ni][1] - mn0);
                s[ni][2] = __expf(s[ni][2] - mn1);
                s[ni][3] = __expf(s[ni][3] - mn1);
                sum0 += s[ni][0] + s[ni][1];
                sum1 += s[ni][2] + s[ni][3];
            }
            sum0 += __shfl_xor_sync(0xffffffffu, sum0, 1);
            sum0 += __shfl_xor_sync(0xffffffffu, sum0, 2);
            sum1 += __shfl_xor_sync(0xffffffffu, sum1, 1);
            sum1 += __shfl_xor_sync(0xffffffffu, sum1, 2);
            l0 = l0 * al0 + sum0;
            l1 = l1 * al1 + sum1;

#pragma unroll
            for (int ni = 0; ni < 8; ni++) {
                o[ni][0] *= al0; o[ni][1] *= al0;
                o[ni][2] *= al1; o[ni][3] *= al1;
            }

            // ---- O += P V (3-term split), P frags from registers ----
#pragma unroll
            for (int kk = 0; kk < 4; kk++) {
                uint32_t pa_h[4], pa_l[4];
                {
                    float p00 = s[2*kk][0],   p01 = s[2*kk][1];
                    float p10 = s[2*kk][2],   p11 = s[2*kk][3];
                    float p20 = s[2*kk+1][0], p21 = s[2*kk+1][1];
                    float p30 = s[2*kk+1][2], p31 = s[2*kk+1][3];
                    pa_h[0] = pack_bf16(p00, p01);
                    pa_h[1] = pack_bf16(p10, p11);
                    pa_h[2] = pack_bf16(p20, p21);
                    pa_h[3] = pack_bf16(p30, p31);
                    __nv_bfloat162 t;
                    t = *(__nv_bfloat162*)&pa_h[0];
                    pa_l[0] = pack_bf16(p00 - __bfloat162float(t.x), p01 - __bfloat162float(t.y));
                    t = *(__nv_bfloat162*)&pa_h[1];
                    pa_l[1] = pack_bf16(p10 - __bfloat162float(t.x), p11 - __bfloat162float(t.y));
                    t = *(__nv_bfloat162*)&pa_h[2];
                    pa_l[2] = pack_bf16(p20 - __bfloat162float(t.x), p21 - __bfloat162float(t.y));
                    t = *(__nv_bfloat162*)&pa_h[3];
                    pa_l[3] = pack_bf16(p30 - __bfloat162float(t.x), p31 - __bfloat162float(t.y));
                }
                uint32_t vh[8][2], vl[8][2];
#pragma unroll
                for (int p = 0; p < 4; p++) {
                    uint32_t off = (uint32_t)((kk * 16 + v_row) * (AST * 2) + (p * 16 + v_col) * 2);
                    uint32_t r4[4];
                    ldsm_x4_t(r4, sb + SVH + off);
                    vh[p*2][0] = r4[0]; vh[p*2][1] = r4[1];
                    vh[p*2+1][0] = r4[2]; vh[p*2+1][1] = r4[3];
                    ldsm_x4_t(r4, sb + SVL + off);
                    vl[p*2][0] = r4[0]; vl[p*2][1] = r4[1];
                    vl[p*2+1][0] = r4[2]; vl[p*2+1][1] = r4[3];
                }
#pragma unroll
                for (int ni = 0; ni < 8; ni++) {
                    mma16816(o[ni], pa_h, vh[ni]);
                    mma16816(o[ni], pa_l, vh[ni]);
                    mma16816(o[ni], pa_h, vl[ni]);
                }
            }
        }
        __syncthreads();   // uniform; protects K/V smem reuse
    }

    // ---- epilogue: normalize, split to bf16 hi/lo, store ----
    const float inv0 = 1.0f / l0, inv1 = 1.0f / l1;
    const int gr = grow0 + wr + lr;
    const int gcb = h * DH + qc * 2;
#pragma unroll
    for (int ni = 0; ni < 8; ni++) {
        float v0 = o[ni][0] * inv0, v1 = o[ni][1] * inv0;
        float v2 = o[ni][2] * inv1, v3 = o[ni][3] * inv1;
        size_t i0 = (size_t)gr * NX + gcb + ni * 8;
        size_t i1 = (size_t)(gr + 8) * NX + gcb + ni * 8;
        uint32_t h0 = pack_bf16(v0, v1);
        uint32_t h1 = pack_bf16(v2, v3);
        *(uint32_t*)(ohi_ + i0) = h0;
        *(uint32_t*)(ohi_ + i1) = h1;
        __nv_bfloat162 t0 = *(__nv_bfloat162*)&h0;
        __nv_bfloat162 t1 = *(__nv_bfloat162*)&h1;
        *(uint32_t*)(olo_ + i0) = pack_bf16(v0 - __bfloat162float(t0.x), v1 - __bfloat162float(t0.y));
        *(uint32_t*)(olo_ + i1) = pack_bf16(v2 - __bfloat162float(t1.x), v3 - __bfloat162float(t1.y));
    }
}

// =====================================================================
// weight transpose + bf16 split
// =====================================================================
__global__ __launch_bounds__(256) void tsplit_kernel(
    const float* __restrict__ W, __nv_bfloat16* __restrict__ hi,
    __nv_bfloat16* __restrict__ lo, int K, int N)
{
    __shared__ float t[32][33];
    const int n0 = blockIdx.x * 32, k0 = blockIdx.y * 32;
    const int tx = threadIdx.x & 31, ty = threadIdx.x >> 5;
#pragma unroll
    for (int i = 0; i < 32; i += 8)
        t[ty + i][tx] = W[(size_t)(k0 + ty + i) * N + n0 + tx];
    __syncthreads();
#pragma unroll
    for (int i = 0; i < 32; i += 8) {
        float v = t[tx][ty + i];
        __nv_bfloat16 h = __float2bfloat16(v);
        size_t o = (size_t)(n0 + ty + i) * K + k0 + tx;
        hi[o] = h;
        lo[o] = __float2bfloat16(v - __bfloat162float(h));
    }
}

__global__ __launch_bounds__(256) void split_kernel(
    const float* __restrict__ in, __nv_bfloat16* __restrict__ hi,
    __nv_bfloat16* __restrict__ lo, int n4)
{
    int i = blockIdx.x * blockDim.x + threadIdx.x;
    if (i >= n4) return;
    float4 v = *(const float4*)(in + i * 4);
    __nv_bfloat16 h0 = __float2bfloat16(v.x), h1 = __float2bfloat16(v.y);
    __nv_bfloat16 h2 = __float2bfloat16(v.z), h3 = __float2bfloat16(v.w);
    __nv_bfloat162 p0; p0.x = h0; p0.y = h1;
    __nv_bfloat162 p1; p1.x = h2; p1.y = h3;
    *(__nv_bfloat162*)(hi + i * 4) = p0;
    *(__nv_bfloat162*)(hi + i * 4 + 2) = p1;
    __nv_bfloat162 q0, q1;
    q0.x = __float2bfloat16(v.x - __bfloat162float(h0));
    q0.y = __float2bfloat16(v.y - __bfloat162float(h1));
    q1.x = __float2bfloat16(v.z - __bfloat162float(h2));
    q1.y = __float2bfloat16(v.w - __bfloat162float(h3));
    *(__nv_bfloat162*)(lo + i * 4) = q0;
    *(__nv_bfloat162*)(lo + i * 4 + 2) = q1;
}

// =====================================================================
// LayerNorm (additive, faithful to source bug) + optional bf16 split out
// =====================================================================
__global__ __launch_bounds__(256) void ln_kernel(
    const float* __restrict__ in1, const float* __restrict__ in2,
    const float* __restrict__ g, const float* __restrict__ bb,
    float* __restrict__ out, __nv_bfloat16* __restrict__ ohi,
    __nv_bfloat16* __restrict__ olo)
{
    __shared__ float buf[NX];
    __shared__ float red[256];
    __shared__ float red2[256];

    const int row = blockIdx.x;
    const int tid = threadIdx.x;
    const size_t base = (size_t)row * NX;

    float s = 0.0f, s2 = 0.0f;
#pragma unroll
    for (int k = 0; k < 3; k++) {
        int i = tid + k * 256;
        float v = in1[base + i] + in2[base + i];
        buf[i] = v;
        s += v; s2 += v * v;
    }
    red[tid] = s; red2[tid] = s2;
    __syncthreads();
    for (int off = 128; off > 0; off >>= 1) {
        if (tid < off) { red[tid] += red[tid + off]; red2[tid] += red2[tid + off]; }
        __syncthreads();
    }
    const float u = red[0] * (1.0f / NX);
    const float var = red2[0] * (1.0f / NX) - u * u;
    const float rstd = rsqrtf(var + EPS);
#pragma unroll
    for (int k = 0; k < 3; k++) {
        int i = tid + k * 256;
        float v = g[i] + (buf[i] - u) * rstd + bb[i];
        out[base + i] = v;
        if (ohi) {
            __nv_bfloat16 h = __float2bfloat16(v);
            ohi[base + i] = h;
            olo[base + i] = __float2bfloat16(v - __bfloat162float(h));
        }
    }
}

// =====================================================================
extern "C" void kernel_launch(void* const* d_in, const int* in_sizes, int n_in,
                              void* d_out, int out_size)
{
    const float* x      = (const float*)d_in[0];
    const float* w_attn = (const float*)d_in[1];
    const float* b_attn = (const float*)d_in[2];
    const float* w_proj = (const float*)d_in[3];
    const float* b_proj = (const float*)d_in[4];
    const float* ln1_g  = (const float*)d_in[5];
    const float* ln1_b  = (const float*)d_in[6];
    const float* w_fc   = (const float*)d_in[7];
    const float* b_fc   = (const float*)d_in[8];
    const float* w_fc2  = (const float*)d_in[9];
    const float* b_fc2  = (const float*)d_in[10];
    const float* ln2_g  = (const float*)d_in[11];
    const float* ln2_b  = (const float*)d_in[12];
    float* out = (float*)d_out;

    float *nbuf, *tmp;
    __nv_bfloat16 *ahi, *alo, *hhi, *hlo, *whi, *wlo;
    cudaGetSymbolAddress((void**)&nbuf, g_n);
    cudaGetSymbolAddress((void**)&tmp,  g_tmp);
    cudaGetSymbolAddress((void**)&ahi,  g_ahi);
    cudaGetSymbolAddress((void**)&alo,  g_alo);
    cudaGetSymbolAddress((void**)&hhi,  g_hhi);
    cudaGetSymbolAddress((void**)&hlo,  g_hlo);
    cudaGetSymbolAddress((void**)&whi,  g_whi);
    cudaGetSymbolAddress((void**)&wlo,  g_wlo);

    static int smem_set = 0;
    if (!smem_set) {
        cudaFuncSetAttribute(gemm_tc_kernel,
                             cudaFuncAttributeMaxDynamicSharedMemorySize, GEMM_DSMEM);
        cudaFuncSetAttribute(attn_mma_kernel,
                             cudaFuncAttributeMaxDynamicSharedMemorySize, ATTN_DSMEM);
        smem_set = 1;
    }

    // --- weight prep ---
    tsplit_kernel<<<dim3(3 * NX / 32, NX / 32), 256>>>(w_attn, whi + WOFF_ATTN, wlo + WOFF_ATTN, NX, 3 * NX);
    tsplit_kernel<<<dim3(NX / 32, NX / 32),     256>>>(w_proj, whi + WOFF_PROJ, wlo + WOFF_PROJ, NX, NX);
    tsplit_kernel<<<dim3(4 * NX / 32, NX / 32), 256>>>(w_fc,   whi + WOFF_FC,   wlo + WOFF_FC,   NX, 4 * NX);
    tsplit_kernel<<<dim3(NX / 32, 4 * NX / 32), 256>>>(w_fc2,  whi + WOFF_FC2,  wlo + WOFF_FC2,  4 * NX, NX);

    // --- x split ---
    split_kernel<<<(MROWS * NX / 4 + 255) / 256, 256>>>(x, ahi, alo, MROWS * NX / 4);

    // 1. qkv = x @ w_attn + b_attn  -> bf16 hi/lo directly (hhi/hlo)
    gemm_tc_kernel<<<dim3(3 * NX / 128, MROWS / 128), 256, GEMM_DSMEM>>>(
        ahi, alo, whi + WOFF_ATTN, wlo + WOFF_ATTN, b_attn, nullptr, hhi, hlo,
        MROWS, 3 * NX, NX, 0);

    // 2. attention (HMMA flash) -> attn split (ahi/alo)
    attn_mma_kernel<<<dim3(NCTX / 128, NHEAD, BATCH), 256, ATTN_DSMEM>>>(
        hhi, hlo, ahi, alo);

    // 3. proj = attn @ w_proj + b_proj -> tmp fp32
    gemm_tc_kernel<<<dim3(NX / 128, MROWS / 128), 256, GEMM_DSMEM>>>(
        ahi, alo, whi + WOFF_PROJ, wlo + WOFF_PROJ, b_proj, tmp, nullptr, nullptr,
        MROWS, NX, NX, 0);

    // 4. n = LN(x + proj) (+ split)
    ln_kernel<<<MROWS, 256>>>(x, tmp, ln1_g, ln1_b, nbuf, ahi, alo);

    // 5. h = relu(n @ w_fc + b_fc) -> split only
    gemm_tc_kernel<<<dim3(4 * NX / 128, MROWS / 128), 256, GEMM_DSMEM>>>(
        ahi, alo, whi + WOFF_FC, wlo + WOFF_FC, b_fc, nullptr, hhi, hlo,
        MROWS, 4 * NX, NX, 1);

    // 6. m = h @ w_fc2 + b_fc2 -> tmp
    gemm_tc_kernel<<<dim3(NX / 128, MROWS / 128), 256, GEMM_DSMEM>>>(
        hhi, hlo, whi + WOFF_FC2, wlo + WOFF_FC2, b_fc2, tmp, nullptr, nullptr,
        MROWS, NX, 4 * NX, 0);

    // 7. out = LN(n + m)
    ln_kernel<<<MROWS, 256>>>(nbuf, tmp, ln2_g, ln2_b, out, nullptr, nullptr);
}

// round 6
// speedup vs baseline: 3.1042x; 1.1076x over previous
#include <cuda_runtime.h>
#include <cuda_bf16.h>
#include <math.h>
#include <stdint.h>

// Problem constants
#define NX     768
#define NHEAD  12
#define DH     64
#define NCTX   2048
#define BATCH  4
#define MROWS  (BATCH * NCTX)        // 8192
#define EPS    1e-5f
#define NEGBIG -1000000000.0f

// ---------------- scratch (no allocations allowed) ----------------
__device__ float g_n   [MROWS * NX];
__device__ float g_tmp [MROWS * NX];
__device__ __nv_bfloat16 g_ahi[MROWS * NX];
__device__ __nv_bfloat16 g_alo[MROWS * NX];
__device__ __nv_bfloat16 g_hhi[MROWS * 4 * NX];   // also holds qkv split (2304<=3072)
__device__ __nv_bfloat16 g_hlo[MROWS * 4 * NX];
#define WOFF_ATTN 0
#define WOFF_PROJ (3*NX*NX)
#define WOFF_FC   (WOFF_PROJ + NX*NX)
#define WOFF_FC2  (WOFF_FC + 4*NX*NX)
#define WTOTAL    (WOFF_FC2 + 4*NX*NX)
__device__ __nv_bfloat16 g_whi[WTOTAL];
__device__ __nv_bfloat16 g_wlo[WTOTAL];

// =====================================================================
// helpers
// =====================================================================
__device__ __forceinline__ uint32_t smem_u32(const void* p) {
    uint32_t a;
    asm("{ .reg .u64 t; cvta.to.shared.u64 t, %1; cvt.u32.u64 %0, t; }" : "=r"(a) : "l"(p));
    return a;
}
__device__ __forceinline__ void cp_async16(uint32_t s, const void* g) {
    asm volatile("cp.async.cg.shared.global [%0], [%1], 16;\n"
                 :: "r"(s), "l"(__cvta_generic_to_global(g)));
}
#define CP_COMMIT()   asm volatile("cp.async.commit_group;\n" ::: "memory")
#define CP_WAIT(n)    asm volatile("cp.async.wait_group %0;\n" :: "n"(n) : "memory")

__device__ __forceinline__ void ldsm_x4(uint32_t* r, uint32_t addr) {
    asm volatile("ldmatrix.sync.aligned.m8n8.x4.shared.b16 {%0,%1,%2,%3}, [%4];"
                 : "=r"(r[0]), "=r"(r[1]), "=r"(r[2]), "=r"(r[3]) : "r"(addr));
}
__device__ __forceinline__ void ldsm_x4_t(uint32_t* r, uint32_t addr) {
    asm volatile("ldmatrix.sync.aligned.m8n8.x4.trans.shared.b16 {%0,%1,%2,%3}, [%4];"
                 : "=r"(r[0]), "=r"(r[1]), "=r"(r[2]), "=r"(r[3]) : "r"(addr));
}
__device__ __forceinline__ void mma16816(float* d, const uint32_t* a, const uint32_t* b) {
    asm volatile(
        "mma.sync.aligned.m16n8k16.row.col.f32.bf16.bf16.f32 "
        "{%0,%1,%2,%3}, {%4,%5,%6,%7}, {%8,%9}, {%0,%1,%2,%3};"
        : "+f"(d[0]), "+f"(d[1]), "+f"(d[2]), "+f"(d[3])
        : "r"(a[0]), "r"(a[1]), "r"(a[2]), "r"(a[3]), "r"(b[0]), "r"(b[1]));
}
__device__ __forceinline__ uint32_t pack_bf16(float lo, float hi) {
    __nv_bfloat162 t = __floats2bfloat162_rn(lo, hi);
    return *reinterpret_cast<uint32_t*>(&t);
}

// =====================================================================
// HMMA split-bf16 GEMM — now 2 CTAs/SM
// =====================================================================
#define ST     40
#define TILEB  (128 * ST * 2)
#define STAGEB (4 * TILEB)
#define GEMM_DSMEM (2 * STAGEB)

__global__ __launch_bounds__(256, 2) void gemm_tc_kernel(
    const __nv_bfloat16* __restrict__ Ahi, const __nv_bfloat16* __restrict__ Alo,
    const __nv_bfloat16* __restrict__ Bhi, const __nv_bfloat16* __restrict__ Blo,
    const float* __restrict__ bias,
    float* __restrict__ C, __nv_bfloat16* __restrict__ Hhi, __nv_bfloat16* __restrict__ Hlo,
    int M, int N, int K, int relu)
{
    extern __shared__ __align__(16) char dsm[];
    const uint32_t sbase = smem_u32(dsm);

    const int tid  = threadIdx.x;
    const int wid  = tid >> 5;
    const int lane = tid & 31;
    const int wm   = wid >> 2;
    const int wn   = wid & 3;
    const int row0 = blockIdx.y * 128;
    const int col0 = blockIdx.x * 128;

    float acc[4][4][4];
#pragma unroll
    for (int mi = 0; mi < 4; mi++)
#pragma unroll
        for (int ni = 0; ni < 4; ni++)
#pragma unroll
            for (int j = 0; j < 4; j++) acc[mi][ni][j] = 0.0f;

    const int nchunks = K >> 5;

    auto load_stage = [&](int i) {
        const uint32_t st = sbase + (i & 1) * STAGEB;
        const int kt = i << 5;
#pragma unroll 2
        for (int u = tid; u < 512; u += 256) {
            int r = u >> 2, c = u & 3;
            uint32_t off = (uint32_t)(r * (ST * 2) + c * 16);
            size_t ga = (size_t)(row0 + r) * K + kt + c * 8;
            size_t gb = (size_t)(col0 + r) * K + kt + c * 8;
            cp_async16(st + off,              Ahi + ga);
            cp_async16(st + TILEB + off,      Alo + ga);
            cp_async16(st + 2 * TILEB + off,  Bhi + gb);
            cp_async16(st + 3 * TILEB + off,  Blo + gb);
        }
        CP_COMMIT();
    };

    load_stage(0);

    const int lr8 = lane & 7;
    const int lg  = lane >> 3;
    const int a_row = lr8 + (lg & 1) * 8;
    const int a_col = (lg >> 1) * 8;
    const int b_rowg = (lg >> 1) * 8 + lr8;
    const int b_colg = (lg & 1) * 8;

    for (int i = 0; i < nchunks; i++) {
        if (i + 1 < nchunks) { load_stage(i + 1); CP_WAIT(1); }
        else                 { CP_WAIT(0); }
        __syncthreads();

        const uint32_t st  = sbase + (i & 1) * STAGEB;
        const uint32_t sAh = st;
        const uint32_t sAl = st + TILEB;
        const uint32_t sBh = st + 2 * TILEB;
        const uint32_t sBl = st + 3 * TILEB;

#pragma unroll
        for (int ks = 0; ks < 2; ks++) {
            const int kc = ks * 16;
            uint32_t bhi[4][2], blo[4][2];
#pragma unroll
            for (int p = 0; p < 2; p++) {
                int nrow = wn * 32 + p * 16 + b_rowg;
                uint32_t off = (uint32_t)(nrow * (ST * 2) + (kc + b_colg) * 2);
                uint32_t r4[4];
                ldsm_x4(r4, sBh + off);
                bhi[p*2][0] = r4[0]; bhi[p*2][1] = r4[1];
                bhi[p*2+1][0] = r4[2]; bhi[p*2+1][1] = r4[3];
                ldsm_x4(r4, sBl + off);
                blo[p*2][0] = r4[0]; blo[p*2][1] = r4[1];
                blo[p*2+1][0] = r4[2]; blo[p*2+1][1] = r4[3];
            }
#pragma unroll
            for (int mi = 0; mi < 4; mi++) {
                int mrow = wm * 64 + mi * 16 + a_row;
                uint32_t off = (uint32_t)(mrow * (ST * 2) + (kc + a_col) * 2);
                uint32_t ah[4], al[4];
                ldsm_x4(ah, sAh + off);
                ldsm_x4(al, sAl + off);
#pragma unroll
                for (int ni = 0; ni < 4; ni++) {
                    mma16816(acc[mi][ni], ah, bhi[ni]);
                    mma16816(acc[mi][ni], al, bhi[ni]);
                    mma16816(acc[mi][ni], ah, blo[ni]);
                }
            }
        }
        __syncthreads();
    }

    float* sof = (float*)dsm;
    const int qr = lane >> 2;
    const int qc2 = (lane & 3) * 2;
#pragma unroll
    for (int mi = 0; mi < 4; mi++) {
#pragma unroll
        for (int ni = 0; ni < 4; ni++) {
            int r = wm * 64 + mi * 16 + qr;
            int c = wn * 32 + ni * 8 + qc2;
            *(float2*)(sof + r * 132 + c)       = make_float2(acc[mi][ni][0], acc[mi][ni][1]);
            *(float2*)(sof + (r + 8) * 132 + c) = make_float2(acc[mi][ni][2], acc[mi][ni][3]);
        }
    }
    __syncthreads();

    for (int i = tid; i < 128 * 32; i += 256) {
        int r = i >> 5, cu = i & 31;
        float4 v = *(float4*)(sof + r * 132 + cu * 4);
        int gcol = col0 + cu * 4;
        float4 bb = *(const float4*)(bias + gcol);
        v.x += bb.x; v.y += bb.y; v.z += bb.z; v.w += bb.w;
        if (relu) {
            v.x = fmaxf(v.x, 0.0f); v.y = fmaxf(v.y, 0.0f);
            v.z = fmaxf(v.z, 0.0f); v.w = fmaxf(v.w, 0.0f);
        }
        size_t gi = (size_t)(row0 + r) * N + gcol;
        if (C) *(float4*)(C + gi) = v;
        if (Hhi) {
            __nv_bfloat16 h0 = __float2bfloat16(v.x), h1 = __float2bfloat16(v.y);
            __nv_bfloat16 h2 = __float2bfloat16(v.z), h3 = __float2bfloat16(v.w);
            __nv_bfloat162 p0; p0.x = h0; p0.y = h1;
            __nv_bfloat162 p1; p1.x = h2; p1.y = h3;
            *(__nv_bfloat162*)(Hhi + gi) = p0;
            *(__nv_bfloat162*)(Hhi + gi + 2) = p1;
            __nv_bfloat162 q0, q1;
            q0.x = __float2bfloat16(v.x - __bfloat162float(h0));
            q0.y = __float2bfloat16(v.y - __bfloat162float(h1));
            q1.x = __float2bfloat16(v.z - __bfloat162float(h2));
            q1.y = __float2bfloat16(v.w - __bfloat162float(h3));
            *(__nv_bfloat162*)(Hlo + gi) = q0;
            *(__nv_bfloat162*)(Hlo + gi + 2) = q1;
        }
    }
}

// =====================================================================
// HMMA flash attention (causal, NO scale), split-bf16 numerics.
// =====================================================================
#define AST    72
#define A_Q_BYTES (128 * AST * 2)
#define A_KV_BYTES (64 * AST * 2)
#define SQH 0
#define SQL (A_Q_BYTES)
#define SKH (2 * A_Q_BYTES)
#define SKL (2 * A_Q_BYTES + A_KV_BYTES)
#define SVH (2 * A_Q_BYTES + 2 * A_KV_BYTES)
#define SVL (2 * A_Q_BYTES + 3 * A_KV_BYTES)
#define ATTN_DSMEM (2 * A_Q_BYTES + 4 * A_KV_BYTES)

__global__ __launch_bounds__(256) void attn_mma_kernel(
    const __nv_bfloat16* __restrict__ qh_, const __nv_bfloat16* __restrict__ ql_,
    __nv_bfloat16* __restrict__ ohi_, __nv_bfloat16* __restrict__ olo_)
{
    extern __shared__ __align__(16) char dsm[];
    const uint32_t sb = smem_u32(dsm);

    const int tid  = threadIdx.x;
    const int wid  = tid >> 5;
    const int lane = tid & 31;
    const int it = blockIdx.x;
    const int h  = blockIdx.y;
    const int b  = blockIdx.z;
    const int row0  = it * 128;
    const int grow0 = b * NCTX + row0;

    for (int u = tid; u < 1024; u += 256) {
        int r = u >> 3, c = u & 7;
        uint32_t off = (uint32_t)(r * (AST * 2) + c * 16);
        size_t gi = (size_t)(grow0 + r) * (3 * NX) + h * DH + c * 8;
        cp_async16(sb + SQH + off, qh_ + gi);
        cp_async16(sb + SQL + off, ql_ + gi);
    }
    CP_COMMIT();

    const int wr  = wid * 16;
    const int lr  = lane >> 2;
    const int qc  = lane & 3;
    const int lr8 = lane & 7;
    const int lg  = lane >> 3;
    const int a_row = lr8 + (lg & 1) * 8;
    const int a_col = (lg >> 1) * 8;
    const int b_rowg = (lg >> 1) * 8 + lr8;
    const int b_colg = (lg & 1) * 8;
    const int v_row = (lg & 1) * 8 + lr8;
    const int v_col = (lg >> 1) * 8;

    CP_WAIT(0);
    __syncthreads();

    uint32_t qh[4][4], ql[4][4];
#pragma unroll
    for (int kk = 0; kk < 4; kk++) {
        uint32_t off = (uint32_t)((wr + a_row) * (AST * 2) + (kk * 16 + a_col) * 2);
        ldsm_x4(qh[kk], sb + SQH + off);
        ldsm_x4(ql[kk], sb + SQL + off);
    }

    float m0 = -INFINITY, m1 = -INFINITY, l0 = 0.0f, l1 = 0.0f;
    float o[8][4];
#pragma unroll
    for (int ni = 0; ni < 8; ni++)
#pragma unroll
        for (int e = 0; e < 4; e++) o[ni][e] = 0.0f;

    const int jmax = 2 * it + 1;
    for (int jt = 0; jt <= jmax; jt++) {
        for (int u = tid; u < 512; u += 256) {
            int r = u >> 3, c = u & 7;
            uint32_t off = (uint32_t)(r * (AST * 2) + c * 16);
            size_t gk = (size_t)(b * NCTX + jt * 64 + r) * (3 * NX) + NX + h * DH + c * 8;
            cp_async16(sb + SKH + off, qh_ + gk);
            cp_async16(sb + SKL + off, ql_ + gk);
            cp_async16(sb + SVH + off, qh_ + gk + NX);
            cp_async16(sb + SVL + off, ql_ + gk + NX);
        }
        CP_COMMIT(); CP_WAIT(0);
        __syncthreads();

        const int col0 = jt * 64;
        const bool fullmask = col0 > row0 + wr + 15;
        if (!fullmask) {
            float s[8][4];
#pragma unroll
            for (int ni = 0; ni < 8; ni++)
#pragma unroll
                for (int e = 0; e < 4; e++) s[ni][e] = 0.0f;

#pragma unroll
            for (int kk = 0; kk < 4; kk++) {
                uint32_t bh[8][2], bl[8][2];
#pragma unroll
                for (int p = 0; p < 4; p++) {
                    uint32_t off = (uint32_t)((p * 16 + b_rowg) * (AST * 2) + (kk * 16 + b_colg) * 2);
                    uint32_t r4[4];
                    ldsm_x4(r4, sb + SKH + off);
                    bh[p*2][0] = r4[0]; bh[p*2][1] = r4[1];
                    bh[p*2+1][0] = r4[2]; bh[p*2+1][1] = r4[3];
                    ldsm_x4(r4, sb + SKL + off);
                    bl[p*2][0] = r4[0]; bl[p*2][1] = r4[1];
                    bl[p*2+1][0] = r4[2]; bl[p*2+1][1] = r4[3];
                }
#pragma unroll
                for (int ni = 0; ni < 8; ni++) {
                    mma16816(s[ni], qh[kk], bh[ni]);
                    mma16816(s[ni], ql[kk], bh[ni]);
                    mma16816(s[ni], qh[kk], bl[ni]);
                }
            }

            if (col0 + 63 > row0 + wr) {
                const int gr0 = row0 + wr + lr;
#pragma unroll
                for (int ni = 0; ni < 8; ni++) {
                    int gc = col0 + ni * 8 + qc * 2;
                    if (gc > gr0)         s[ni][0] = NEGBIG;
                    if (gc + 1 > gr0)     s[ni][1] = NEGBIG;
                    if (gc > gr0 + 8)     s[ni][2] = NEGBIG;
                    if (gc + 1 > gr0 + 8) s[ni][3] = NEGBIG;
                }
            }

            float mt0 = s[0][0], mt1 = s[0][2];
#pragma unroll
            for (int ni = 0; ni < 8; ni++) {
                mt0 = fmaxf(mt0, fmaxf(s[ni][0], s[ni][1]));
                mt1 = fmaxf(mt1, fmaxf(s[ni][2], s[ni][3]));
            }
            mt0 = fmaxf(mt0, __shfl_xor_sync(0xffffffffu, mt0, 1));
            mt0 = fmaxf(mt0, __shfl_xor_sync(0xffffffffu, mt0, 2));
            mt1 = fmaxf(mt1, __shfl_xor_sync(0xffffffffu, mt1, 1));
            mt1 = fmaxf(mt1, __shfl_xor_sync(0xffffffffu, mt1, 2));
            float mn0 = fmaxf(m0, mt0), mn1 = fmaxf(m1, mt1);
            float al0 = __expf(m0 - mn0), al1 = __expf(m1 - mn1);
            m0 = mn0; m1 = mn1;

            float sum0 = 0.0f, sum1 = 0.0f;
#pragma unroll
            for (int ni = 0; ni < 8; ni++) {
                s[ni][0] = __expf(s[ni][0] - mn0);
                s[ni][1] = __expf(s[ni][1] - mn0);
                s[ni][2] = __expf(s[ni][2] - mn1);
                s[ni][3] = __expf(s[ni][3] - mn1);
                sum0 += s[ni][0] + s[ni][1];
                sum1 += s[ni][2] + s[ni][3];
            }
            sum0 += __shfl_xor_sync(0xffffffffu, sum0, 1);
            sum0 += __shfl_xor_sync(0xffffffffu, sum0, 2);
            sum1 += __shfl_xor_sync(0xffffffffu, sum1, 1);
            sum1 += __shfl_xor_sync(0xffffffffu, sum1, 2);
            l0 = l0 * al0 + sum0;
            l1 = l1 * al1 + sum1;

#pragma unroll
            for (int ni = 0; ni < 8; ni++) {
                o[ni][0] *= al0; o[ni][1] *= al0;
                o[ni][2] *= al1; o[ni][3] *= al1;
            }

#pragma unroll
            for (int kk = 0; kk < 4; kk++) {
                uint32_t pa_h[4], pa_l[4];
                {
                    float p00 = s[2*kk][0],   p01 = s[2*kk][1];
                    float p10 = s[2*kk][2],   p11 = s[2*kk][3];
                    float p20 = s[2*kk+1][0], p21 = s[2*kk+1][1];
                    float p30 = s[2*kk+1][2], p31 = s[2*kk+1][3];
                    pa_h[0] = pack_bf16(p00, p01);
                    pa_h[1] = pack_bf16(p10, p11);
                    pa_h[2] = pack_bf16(p20, p21);
                    pa_h[3] = pack_bf16(p30, p31);
                    __nv_bfloat162 t;
                    t = *(__nv_bfloat162*)&pa_h[0];
                    pa_l[0] = pack_bf16(p00 - __bfloat162float(t.x), p01 - __bfloat162float(t.y));
                    t = *(__nv_bfloat162*)&pa_h[1];
                    pa_l[1] = pack_bf16(p10 - __bfloat162float(t.x), p11 - __bfloat162float(t.y));
                    t = *(__nv_bfloat162*)&pa_h[2];
                    pa_l[2] = pack_bf16(p20 - __bfloat162float(t.x), p21 - __bfloat162float(t.y));
                    t = *(__nv_bfloat162*)&pa_h[3];
                    pa_l[3] = pack_bf16(p30 - __bfloat162float(t.x), p31 - __bfloat162float(t.y));
                }
                uint32_t vh[8][2], vl[8][2];
#pragma unroll
                for (int p = 0; p < 4; p++) {
                    uint32_t off = (uint32_t)((kk * 16 + v_row) * (AST * 2) + (p * 16 + v_col) * 2);
                    uint32_t r4[4];
                    ldsm_x4_t(r4, sb + SVH + off);
                    vh[p*2][0] = r4[0]; vh[p*2][1] = r4[1];
                    vh[p*2+1][0] = r4[2]; vh[p*2+1][1] = r4[3];
                    ldsm_x4_t(r4, sb + SVL + off);
                    vl[p*2][0] = r4[0]; vl[p*2][1] = r4[1];
                    vl[p*2+1][0] = r4[2]; vl[p*2+1][1] = r4[3];
                }
#pragma unroll
                for (int ni = 0; ni < 8; ni++) {
                    mma16816(o[ni], pa_h, vh[ni]);
                    mma16816(o[ni], pa_l, vh[ni]);
                    mma16816(o[ni], pa_h, vl[ni]);
                }
            }
        }
        __syncthreads();
    }

    const float inv0 = 1.0f / l0, inv1 = 1.0f / l1;
    const int gr = grow0 + wr + lr;
    const int gcb = h * DH + qc * 2;
#pragma unroll
    for (int ni = 0; ni < 8; ni++) {
        float v0 = o[ni][0] * inv0, v1 = o[ni][1] * inv0;
        float v2 = o[ni][2] * inv1, v3 = o[ni][3] * inv1;
        size_t i0 = (size_t)gr * NX + gcb + ni * 8;
        size_t i1 = (size_t)(gr + 8) * NX + gcb + ni * 8;
        uint32_t h0 = pack_bf16(v0, v1);
        uint32_t h1 = pack_bf16(v2, v3);
        *(uint32_t*)(ohi_ + i0) = h0;
        *(uint32_t*)(ohi_ + i1) = h1;
        __nv_bfloat162 t0 = *(__nv_bfloat162*)&h0;
        __nv_bfloat162 t1 = *(__nv_bfloat162*)&h1;
        *(uint32_t*)(olo_ + i0) = pack_bf16(v0 - __bfloat162float(t0.x), v1 - __bfloat162float(t0.y));
        *(uint32_t*)(olo_ + i1) = pack_bf16(v2 - __bfloat162float(t1.x), v3 - __bfloat162float(t1.y));
    }
}

// =====================================================================
// weight transpose + bf16 split
// =====================================================================
__global__ __launch_bounds__(256) void tsplit_kernel(
    const float* __restrict__ W, __nv_bfloat16* __restrict__ hi,
    __nv_bfloat16* __restrict__ lo, int K, int N)
{
    __shared__ float t[32][33];
    const int n0 = blockIdx.x * 32, k0 = blockIdx.y * 32;
    const int tx = threadIdx.x & 31, ty = threadIdx.x >> 5;
#pragma unroll
    for (int i = 0; i < 32; i += 8)
        t[ty + i][tx] = W[(size_t)(k0 + ty + i) * N + n0 + tx];
    __syncthreads();
#pragma unroll
    for (int i = 0; i < 32; i += 8) {
        float v = t[tx][ty + i];
        __nv_bfloat16 h = __float2bfloat16(v);
        size_t o = (size_t)(n0 + ty + i) * K + k0 + tx;
        hi[o] = h;
        lo[o] = __float2bfloat16(v - __bfloat162float(h));
    }
}

__global__ __launch_bounds__(256) void split_kernel(
    const float* __restrict__ in, __nv_bfloat16* __restrict__ hi,
    __nv_bfloat16* __restrict__ lo, int n4)
{
    int i = blockIdx.x * blockDim.x + threadIdx.x;
    if (i >= n4) return;
    float4 v = *(const float4*)(in + i * 4);
    __nv_bfloat16 h0 = __float2bfloat16(v.x), h1 = __float2bfloat16(v.y);
    __nv_bfloat16 h2 = __float2bfloat16(v.z), h3 = __float2bfloat16(v.w);
    __nv_bfloat162 p0; p0.x = h0; p0.y = h1;
    __nv_bfloat162 p1; p1.x = h2; p1.y = h3;
    *(__nv_bfloat162*)(hi + i * 4) = p0;
    *(__nv_bfloat162*)(hi + i * 4 + 2) = p1;
    __nv_bfloat162 q0, q1;
    q0.x = __float2bfloat16(v.x - __bfloat162float(h0));
    q0.y = __float2bfloat16(v.y - __bfloat162float(h1));
    q1.x = __float2bfloat16(v.z - __bfloat162float(h2));
    q1.y = __float2bfloat16(v.w - __bfloat162float(h3));
    *(__nv_bfloat162*)(lo + i * 4) = q0;
    *(__nv_bfloat162*)(lo + i * 4 + 2) = q1;
}

// =====================================================================
// LayerNorm (additive, faithful to source bug) + optional bf16 split out
// warp-shuffle reduction version
// =====================================================================
__global__ __launch_bounds__(256) void ln_kernel(
    const float* __restrict__ in1, const float* __restrict__ in2,
    const float* __restrict__ g, const float* __restrict__ bb,
    float* __restrict__ out, __nv_bfloat16* __restrict__ ohi,
    __nv_bfloat16* __restrict__ olo)
{
    __shared__ float buf[NX];
    __shared__ float wsum[8], wsum2[8];

    const int row = blockIdx.x;
    const int tid = threadIdx.x;
    const int lane = tid & 31;
    const int wrp = tid >> 5;
    const size_t base = (size_t)row * NX;

    float s = 0.0f, s2 = 0.0f;
#pragma unroll
    for (int k = 0; k < 3; k++) {
        int i = tid + k * 256;
        float v = in1[base + i] + in2[base + i];
        buf[i] = v;
        s += v; s2 += v * v;
    }
#pragma unroll
    for (int off = 16; off > 0; off >>= 1) {
        s  += __shfl_xor_sync(0xffffffffu, s,  off);
        s2 += __shfl_xor_sync(0xffffffffu, s2, off);
    }
    if (lane == 0) { wsum[wrp] = s; wsum2[wrp] = s2; }
    __syncthreads();
    if (wrp == 0) {
        float a = (lane < 8) ? wsum[lane] : 0.0f;
        float a2 = (lane < 8) ? wsum2[lane] : 0.0f;
#pragma unroll
        for (int off = 4; off > 0; off >>= 1) {
            a  += __shfl_xor_sync(0xffffffffu, a,  off);
            a2 += __shfl_xor_sync(0xffffffffu, a2, off);
        }
        if (lane == 0) { wsum[0] = a; wsum2[0] = a2; }
    }
    __syncthreads();
    const float u = wsum[0] * (1.0f / NX);
    const float var = wsum2[0] * (1.0f / NX) - u * u;
    const float rstd = rsqrtf(var + EPS);
#pragma unroll
    for (int k = 0; k < 3; k++) {
        int i = tid + k * 256;
        float v = g[i] + (buf[i] - u) * rstd + bb[i];
        out[base + i] = v;
        if (ohi) {
            __nv_bfloat16 h = __float2bfloat16(v);
            ohi[base + i] = h;
            olo[base + i] = __float2bfloat16(v - __bfloat162float(h));
        }
    }
}

// =====================================================================
extern "C" void kernel_launch(void* const* d_in, const int* in_sizes, int n_in,
                              void* d_out, int out_size)
{
    const float* x      = (const float*)d_in[0];
    const float* w_attn = (const float*)d_in[1];
    const float* b_attn = (const float*)d_in[2];
    const float* w_proj = (const float*)d_in[3];
    const float* b_proj = (const float*)d_in[4];
    const float* ln1_g  = (const float*)d_in[5];
    const float* ln1_b  = (const float*)d_in[6];
    const float* w_fc   = (const float*)d_in[7];
    const float* b_fc   = (const float*)d_in[8];
    const float* w_fc2  = (const float*)d_in[9];
    const float* b_fc2  = (const float*)d_in[10];
    const float* ln2_g  = (const float*)d_in[11];
    const float* ln2_b  = (const float*)d_in[12];
    float* out = (float*)d_out;

    float *nbuf, *tmp;
    __nv_bfloat16 *ahi, *alo, *hhi, *hlo, *whi, *wlo;
    cudaGetSymbolAddress((void**)&nbuf, g_n);
    cudaGetSymbolAddress((void**)&tmp,  g_tmp);
    cudaGetSymbolAddress((void**)&ahi,  g_ahi);
    cudaGetSymbolAddress((void**)&alo,  g_alo);
    cudaGetSymbolAddress((void**)&hhi,  g_hhi);
    cudaGetSymbolAddress((void**)&hlo,  g_hlo);
    cudaGetSymbolAddress((void**)&whi,  g_whi);
    cudaGetSymbolAddress((void**)&wlo,  g_wlo);

    static int smem_set = 0;
    if (!smem_set) {
        cudaFuncSetAttribute(gemm_tc_kernel,
                             cudaFuncAttributeMaxDynamicSharedMemorySize, GEMM_DSMEM);
        cudaFuncSetAttribute(attn_mma_kernel,
                             cudaFuncAttributeMaxDynamicSharedMemorySize, ATTN_DSMEM);
        smem_set = 1;
    }

    // --- weight prep ---
    tsplit_kernel<<<dim3(3 * NX / 32, NX / 32), 256>>>(w_attn, whi + WOFF_ATTN, wlo + WOFF_ATTN, NX, 3 * NX);
    tsplit_kernel<<<dim3(NX / 32, NX / 32),     256>>>(w_proj, whi + WOFF_PROJ, wlo + WOFF_PROJ, NX, NX);
    tsplit_kernel<<<dim3(4 * NX / 32, NX / 32), 256>>>(w_fc,   whi + WOFF_FC,   wlo + WOFF_FC,   NX, 4 * NX);
    tsplit_kernel<<<dim3(NX / 32, 4 * NX / 32), 256>>>(w_fc2,  whi + WOFF_FC2,  wlo + WOFF_FC2,  4 * NX, NX);

    // --- x split ---
    split_kernel<<<(MROWS * NX / 4 + 255) / 256, 256>>>(x, ahi, alo, MROWS * NX / 4);

    // 1. qkv = x @ w_attn + b_attn  -> bf16 hi/lo directly
    gemm_tc_kernel<<<dim3(3 * NX / 128, MROWS / 128), 256, GEMM_DSMEM>>>(
        ahi, alo, whi + WOFF_ATTN, wlo + WOFF_ATTN, b_attn, nullptr, hhi, hlo,
        MROWS, 3 * NX, NX, 0);

    // 2. attention (HMMA flash) -> attn split
    attn_mma_kernel<<<dim3(NCTX / 128, NHEAD, BATCH), 256, ATTN_DSMEM>>>(
        hhi, hlo, ahi, alo);

    // 3. proj = attn @ w_proj + b_proj -> tmp fp32
    gemm_tc_kernel<<<dim3(NX / 128, MROWS / 128), 256, GEMM_DSMEM>>>(
        ahi, alo, whi + WOFF_PROJ, wlo + WOFF_PROJ, b_proj, tmp, nullptr, nullptr,
        MROWS, NX, NX, 0);

    // 4. n = LN(x + proj) (+ split)
    ln_kernel<<<MROWS, 256>>>(x, tmp, ln1_g, ln1_b, nbuf, ahi, alo);

    // 5. h = relu(n @ w_fc + b_fc) -> split only
    gemm_tc_kernel<<<dim3(4 * NX / 128, MROWS / 128), 256, GEMM_DSMEM>>>(
        ahi, alo, whi + WOFF_FC, wlo + WOFF_FC, b_fc, nullptr, hhi, hlo,
        MROWS, 4 * NX, NX, 1);

    // 6. m = h @ w_fc2 + b_fc2 -> tmp
    gemm_tc_kernel<<<dim3(NX / 128, MROWS / 128), 256, GEMM_DSMEM>>>(
        hhi, hlo, whi + WOFF_FC2, wlo + WOFF_FC2, b_fc2, tmp, nullptr, nullptr,
        MROWS, NX, 4 * NX, 0);

    // 7. out = LN(n + m)
    ln_kernel<<<MROWS, 256>>>(nbuf, tmp, ln2_g, ln2_b, out, nullptr, nullptr);
}

// round 7
// speedup vs baseline: 4.1143x; 1.3254x over previous
#include <cuda_runtime.h>
#include <cuda_fp16.h>
#include <math.h>
#include <stdint.h>

// Problem constants
#define NX     768
#define NHEAD  12
#define DH     64
#define NCTX   2048
#define BATCH  4
#define MROWS  (BATCH * NCTX)        // 8192
#define EPS    1e-5f
#define NEGBIG -1000000000.0f

// ---------------- scratch (no allocations allowed) ----------------
__device__ float g_n   [MROWS * NX];
__device__ float g_tmp [MROWS * NX];
__device__ __half g_ahi[MROWS * NX];
__device__ __half g_alo[MROWS * NX];
__device__ __half g_hhi[MROWS * 4 * NX];   // also holds qkv split (2304<=3072)
__device__ __half g_hlo[MROWS * 4 * NX];
#define WOFF_ATTN 0
#define WOFF_PROJ (3*NX*NX)
#define WOFF_FC   (WOFF_PROJ + NX*NX)
#define WOFF_FC2  (WOFF_FC + 4*NX*NX)
#define WTOTAL    (WOFF_FC2 + 4*NX*NX)
__device__ __half g_whi[WTOTAL];           // fp16 weights (hi only; 2-term scheme)

// =====================================================================
// helpers
// =====================================================================
__device__ __forceinline__ uint32_t smem_u32(const void* p) {
    uint32_t a;
    asm("{ .reg .u64 t; cvta.to.shared.u64 t, %1; cvt.u32.u64 %0, t; }" : "=r"(a) : "l"(p));
    return a;
}
__device__ __forceinline__ void cp_async16(uint32_t s, const void* g) {
    asm volatile("cp.async.cg.shared.global [%0], [%1], 16;\n"
                 :: "r"(s), "l"(__cvta_generic_to_global(g)));
}
#define CP_COMMIT()   asm volatile("cp.async.commit_group;\n" ::: "memory")
#define CP_WAIT(n)    asm volatile("cp.async.wait_group %0;\n" :: "n"(n) : "memory")

__device__ __forceinline__ void ldsm_x4(uint32_t* r, uint32_t addr) {
    asm volatile("ldmatrix.sync.aligned.m8n8.x4.shared.b16 {%0,%1,%2,%3}, [%4];"
                 : "=r"(r[0]), "=r"(r[1]), "=r"(r[2]), "=r"(r[3]) : "r"(addr));
}
__device__ __forceinline__ void ldsm_x4_t(uint32_t* r, uint32_t addr) {
    asm volatile("ldmatrix.sync.aligned.m8n8.x4.trans.shared.b16 {%0,%1,%2,%3}, [%4];"
                 : "=r"(r[0]), "=r"(r[1]), "=r"(r[2]), "=r"(r[3]) : "r"(addr));
}
__device__ __forceinline__ void mma16816(float* d, const uint32_t* a, const uint32_t* b) {
    asm volatile(
        "mma.sync.aligned.m16n8k16.row.col.f32.f16.f16.f32 "
        "{%0,%1,%2,%3}, {%4,%5,%6,%7}, {%8,%9}, {%0,%1,%2,%3};"
        : "+f"(d[0]), "+f"(d[1]), "+f"(d[2]), "+f"(d[3])
        : "r"(a[0]), "r"(a[1]), "r"(a[2]), "r"(a[3]), "r"(b[0]), "r"(b[1]));
}
__device__ __forceinline__ uint32_t pack_h2(float a, float b) {
    __half2 t = __floats2half2_rn(a, b);
    return *reinterpret_cast<uint32_t*>(&t);
}

// =====================================================================
// HMMA 2-term fp16 GEMM: C = (Ahi+Alo) @ Whi^T + bias
// Tile 128x128x32, 2 CTAs/SM. Stage: Ahi + Alo + Bhi (3 tiles).
// =====================================================================
#define ST     40
#define TILEB  (128 * ST * 2)             // 10240
#define STAGEB (3 * TILEB)                // 30720
#define GEMM_DSMEM 67584                  // max(2*STAGEB, 128*132*4)

__global__ __launch_bounds__(256, 2) void gemm_tc_kernel(
    const __half* __restrict__ Ahi, const __half* __restrict__ Alo,
    const __half* __restrict__ Bhi,
    const float* __restrict__ bias,
    float* __restrict__ C, __half* __restrict__ Hhi, __half* __restrict__ Hlo,
    int M, int N, int K, int relu)
{
    extern __shared__ __align__(16) char dsm[];
    const uint32_t sbase = smem_u32(dsm);

    const int tid  = threadIdx.x;
    const int wid  = tid >> 5;
    const int lane = tid & 31;
    const int wm   = wid >> 2;
    const int wn   = wid & 3;
    const int row0 = blockIdx.y * 128;
    const int col0 = blockIdx.x * 128;

    float acc[4][4][4];
#pragma unroll
    for (int mi = 0; mi < 4; mi++)
#pragma unroll
        for (int ni = 0; ni < 4; ni++)
#pragma unroll
            for (int j = 0; j < 4; j++) acc[mi][ni][j] = 0.0f;

    const int nchunks = K >> 5;

    auto load_stage = [&](int i) {
        const uint32_t st = sbase + (i & 1) * STAGEB;
        const int kt = i << 5;
#pragma unroll 2
        for (int u = tid; u < 512; u += 256) {
            int r = u >> 2, c = u & 3;
            uint32_t off = (uint32_t)(r * (ST * 2) + c * 16);
            size_t ga = (size_t)(row0 + r) * K + kt + c * 8;
            size_t gb = (size_t)(col0 + r) * K + kt + c * 8;
            cp_async16(st + off,              Ahi + ga);
            cp_async16(st + TILEB + off,      Alo + ga);
            cp_async16(st + 2 * TILEB + off,  Bhi + gb);
        }
        CP_COMMIT();
    };

    load_stage(0);

    const int lr8 = lane & 7;
    const int lg  = lane >> 3;
    const int a_row = lr8 + (lg & 1) * 8;
    const int a_col = (lg >> 1) * 8;
    const int b_rowg = (lg >> 1) * 8 + lr8;
    const int b_colg = (lg & 1) * 8;

    for (int i = 0; i < nchunks; i++) {
        if (i + 1 < nchunks) { load_stage(i + 1); CP_WAIT(1); }
        else                 { CP_WAIT(0); }
        __syncthreads();

        const uint32_t st  = sbase + (i & 1) * STAGEB;
        const uint32_t sAh = st;
        const uint32_t sAl = st + TILEB;
        const uint32_t sBh = st + 2 * TILEB;

#pragma unroll
        for (int ks = 0; ks < 2; ks++) {
            const int kc = ks * 16;
            uint32_t bhi[4][2];
#pragma unroll
            for (int p = 0; p < 2; p++) {
                int nrow = wn * 32 + p * 16 + b_rowg;
                uint32_t off = (uint32_t)(nrow * (ST * 2) + (kc + b_colg) * 2);
                uint32_t r4[4];
                ldsm_x4(r4, sBh + off);
                bhi[p*2][0] = r4[0]; bhi[p*2][1] = r4[1];
                bhi[p*2+1][0] = r4[2]; bhi[p*2+1][1] = r4[3];
            }
#pragma unroll
            for (int mi = 0; mi < 4; mi++) {
                int mrow = wm * 64 + mi * 16 + a_row;
                uint32_t off = (uint32_t)(mrow * (ST * 2) + (kc + a_col) * 2);
                uint32_t ah[4], al[4];
                ldsm_x4(ah, sAh + off);
                ldsm_x4(al, sAl + off);
#pragma unroll
                for (int ni = 0; ni < 4; ni++) {
                    mma16816(acc[mi][ni], ah, bhi[ni]);
                    mma16816(acc[mi][ni], al, bhi[ni]);
                }
            }
        }
        __syncthreads();
    }

    float* sof = (float*)dsm;
    const int qr = lane >> 2;
    const int qc2 = (lane & 3) * 2;
#pragma unroll
    for (int mi = 0; mi < 4; mi++) {
#pragma unroll
        for (int ni = 0; ni < 4; ni++) {
            int r = wm * 64 + mi * 16 + qr;
            int c = wn * 32 + ni * 8 + qc2;
            *(float2*)(sof + r * 132 + c)       = make_float2(acc[mi][ni][0], acc[mi][ni][1]);
            *(float2*)(sof + (r + 8) * 132 + c) = make_float2(acc[mi][ni][2], acc[mi][ni][3]);
        }
    }
    __syncthreads();

    for (int i = tid; i < 128 * 32; i += 256) {
        int r = i >> 5, cu = i & 31;
        float4 v = *(float4*)(sof + r * 132 + cu * 4);
        int gcol = col0 + cu * 4;
        float4 bb = *(const float4*)(bias + gcol);
        v.x += bb.x; v.y += bb.y; v.z += bb.z; v.w += bb.w;
        if (relu) {
            v.x = fmaxf(v.x, 0.0f); v.y = fmaxf(v.y, 0.0f);
            v.z = fmaxf(v.z, 0.0f); v.w = fmaxf(v.w, 0.0f);
        }
        size_t gi = (size_t)(row0 + r) * N + gcol;
        if (C) *(float4*)(C + gi) = v;
        if (Hhi) {
            __half h0 = __float2half_rn(v.x), h1 = __float2half_rn(v.y);
            __half h2 = __float2half_rn(v.z), h3 = __float2half_rn(v.w);
            __half2 p0; p0.x = h0; p0.y = h1;
            __half2 p1; p1.x = h2; p1.y = h3;
            *(__half2*)(Hhi + gi) = p0;
            *(__half2*)(Hhi + gi + 2) = p1;
            __half2 q0, q1;
            q0.x = __float2half_rn(v.x - __half2float(h0));
            q0.y = __float2half_rn(v.y - __half2float(h1));
            q1.x = __float2half_rn(v.z - __half2float(h2));
            q1.y = __float2half_rn(v.w - __half2float(h3));
            *(__half2*)(Hlo + gi) = q0;
            *(__half2*)(Hlo + gi + 2) = q1;
        }
    }
}

// =====================================================================
// HMMA flash attention (causal, NO scale), 3-term fp16 split.
// =====================================================================
#define AST    72
#define A_Q_BYTES (128 * AST * 2)
#define A_KV_BYTES (64 * AST * 2)
#define SQH 0
#define SQL (A_Q_BYTES)
#define SKH (2 * A_Q_BYTES)
#define SKL (2 * A_Q_BYTES + A_KV_BYTES)
#define SVH (2 * A_Q_BYTES + 2 * A_KV_BYTES)
#define SVL (2 * A_Q_BYTES + 3 * A_KV_BYTES)
#define ATTN_DSMEM (2 * A_Q_BYTES + 4 * A_KV_BYTES)

__global__ __launch_bounds__(256) void attn_mma_kernel(
    const __half* __restrict__ qh_, const __half* __restrict__ ql_,
    __half* __restrict__ ohi_, __half* __restrict__ olo_)
{
    extern __shared__ __align__(16) char dsm[];
    const uint32_t sb = smem_u32(dsm);

    const int tid  = threadIdx.x;
    const int wid  = tid >> 5;
    const int lane = tid & 31;
    const int it = blockIdx.x;
    const int h  = blockIdx.y;
    const int b  = blockIdx.z;
    const int row0  = it * 128;
    const int grow0 = b * NCTX + row0;

    for (int u = tid; u < 1024; u += 256) {
        int r = u >> 3, c = u & 7;
        uint32_t off = (uint32_t)(r * (AST * 2) + c * 16);
        size_t gi = (size_t)(grow0 + r) * (3 * NX) + h * DH + c * 8;
        cp_async16(sb + SQH + off, qh_ + gi);
        cp_async16(sb + SQL + off, ql_ + gi);
    }
    CP_COMMIT();

    const int wr  = wid * 16;
    const int lr  = lane >> 2;
    const int qc  = lane & 3;
    const int lr8 = lane & 7;
    const int lg  = lane >> 3;
    const int a_row = lr8 + (lg & 1) * 8;
    const int a_col = (lg >> 1) * 8;
    const int b_rowg = (lg >> 1) * 8 + lr8;
    const int b_colg = (lg & 1) * 8;
    const int v_row = (lg & 1) * 8 + lr8;
    const int v_col = (lg >> 1) * 8;

    CP_WAIT(0);
    __syncthreads();

    uint32_t qh[4][4], ql[4][4];
#pragma unroll
    for (int kk = 0; kk < 4; kk++) {
        uint32_t off = (uint32_t)((wr + a_row) * (AST * 2) + (kk * 16 + a_col) * 2);
        ldsm_x4(qh[kk], sb + SQH + off);
        ldsm_x4(ql[kk], sb + SQL + off);
    }

    float m0 = -INFINITY, m1 = -INFINITY, l0 = 0.0f, l1 = 0.0f;
    float o[8][4];
#pragma unroll
    for (int ni = 0; ni < 8; ni++)
#pragma unroll
        for (int e = 0; e < 4; e++) o[ni][e] = 0.0f;

    const int jmax = 2 * it + 1;
    for (int jt = 0; jt <= jmax; jt++) {
        for (int u = tid; u < 512; u += 256) {
            int r = u >> 3, c = u & 7;
            uint32_t off = (uint32_t)(r * (AST * 2) + c * 16);
            size_t gk = (size_t)(b * NCTX + jt * 64 + r) * (3 * NX) + NX + h * DH + c * 8;
            cp_async16(sb + SKH + off, qh_ + gk);
            cp_async16(sb + SKL + off, ql_ + gk);
            cp_async16(sb + SVH + off, qh_ + gk + NX);
            cp_async16(sb + SVL + off, ql_ + gk + NX);
        }
        CP_COMMIT(); CP_WAIT(0);
        __syncthreads();

        const int col0 = jt * 64;
        const bool fullmask = col0 > row0 + wr + 15;
        if (!fullmask) {
            float s[8][4];
#pragma unroll
            for (int ni = 0; ni < 8; ni++)
#pragma unroll
                for (int e = 0; e < 4; e++) s[ni][e] = 0.0f;

#pragma unroll
            for (int kk = 0; kk < 4; kk++) {
                uint32_t bh[8][2], bl[8][2];
#pragma unroll
                for (int p = 0; p < 4; p++) {
                    uint32_t off = (uint32_t)((p * 16 + b_rowg) * (AST * 2) + (kk * 16 + b_colg) * 2);
                    uint32_t r4[4];
                    ldsm_x4(r4, sb + SKH + off);
                    bh[p*2][0] = r4[0]; bh[p*2][1] = r4[1];
                    bh[p*2+1][0] = r4[2]; bh[p*2+1][1] = r4[3];
                    ldsm_x4(r4, sb + SKL + off);
                    bl[p*2][0] = r4[0]; bl[p*2][1] = r4[1];
                    bl[p*2+1][0] = r4[2]; bl[p*2+1][1] = r4[3];
                }
#pragma unroll
                for (int ni = 0; ni < 8; ni++) {
                    mma16816(s[ni], qh[kk], bh[ni]);
                    mma16816(s[ni], ql[kk], bh[ni]);
                    mma16816(s[ni], qh[kk], bl[ni]);
                }
            }

            if (col0 + 63 > row0 + wr) {
                const int gr0 = row0 + wr + lr;
#pragma unroll
                for (int ni = 0; ni < 8; ni++) {
                    int gc = col0 + ni * 8 + qc * 2;
                    if (gc > gr0)         s[ni][0] = NEGBIG;
                    if (gc + 1 > gr0)     s[ni][1] = NEGBIG;
                    if (gc > gr0 + 8)     s[ni][2] = NEGBIG;
                    if (gc + 1 > gr0 + 8) s[ni][3] = NEGBIG;
                }
            }

            float mt0 = s[0][0], mt1 = s[0][2];
#pragma unroll
            for (int ni = 0; ni < 8; ni++) {
                mt0 = fmaxf(mt0, fmaxf(s[ni][0], s[ni][1]));
                mt1 = fmaxf(mt1, fmaxf(s[ni][2], s[ni][3]));
            }
            mt0 = fmaxf(mt0, __shfl_xor_sync(0xffffffffu, mt0, 1));
            mt0 = fmaxf(mt0, __shfl_xor_sync(0xffffffffu, mt0, 2));
            mt1 = fmaxf(mt1, __shfl_xor_sync(0xffffffffu, mt1, 1));
            mt1 = fmaxf(mt1, __shfl_xor_sync(0xffffffffu, mt1, 2));
            float mn0 = fmaxf(m0, mt0), mn1 = fmaxf(m1, mt1);
            float al0 = __expf(m0 - mn0), al1 = __expf(m1 - mn1);
            m0 = mn0; m1 = mn1;

            float sum0 = 0.0f, sum1 = 0.0f;
#pragma unroll
            for (int ni = 0; ni < 8; ni++) {
                s[ni][0] = __expf(s[ni][0] - mn0);
                s[ni][1] = __expf(s[ni][1] - mn0);
                s[ni][2] = __expf(s[ni][2] - mn1);
                s[ni][3] = __expf(s[ni][3] - mn1);
                sum0 += s[ni][0] + s[ni][1];
                sum1 += s[ni][2] + s[ni][3];
            }
            sum0 += __shfl_xor_sync(0xffffffffu, sum0, 1);
            sum0 += __shfl_xor_sync(0xffffffffu, sum0, 2);
            sum1 += __shfl_xor_sync(0xffffffffu, sum1, 1);
            sum1 += __shfl_xor_sync(0xffffffffu, sum1, 2);
            l0 = l0 * al0 + sum0;
            l1 = l1 * al1 + sum1;

#pragma unroll
            for (int ni = 0; ni < 8; ni++) {
                o[ni][0] *= al0; o[ni][1] *= al0;
                o[ni][2] *= al1; o[ni][3] *= al1;
            }

#pragma unroll
            for (int kk = 0; kk < 4; kk++) {
                uint32_t pa_h[4], pa_l[4];
                {
                    float p00 = s[2*kk][0],   p01 = s[2*kk][1];
                    float p10 = s[2*kk][2],   p11 = s[2*kk][3];
                    float p20 = s[2*kk+1][0], p21 = s[2*kk+1][1];
                    float p30 = s[2*kk+1][2], p31 = s[2*kk+1][3];
                    pa_h[0] = pack_h2(p00, p01);
                    pa_h[1] = pack_h2(p10, p11);
                    pa_h[2] = pack_h2(p20, p21);
                    pa_h[3] = pack_h2(p30, p31);
                    __half2 t;
                    t = *(__half2*)&pa_h[0];
                    pa_l[0] = pack_h2(p00 - __half2float(t.x), p01 - __half2float(t.y));
                    t = *(__half2*)&pa_h[1];
                    pa_l[1] = pack_h2(p10 - __half2float(t.x), p11 - __half2float(t.y));
                    t = *(__half2*)&pa_h[2];
                    pa_l[2] = pack_h2(p20 - __half2float(t.x), p21 - __half2float(t.y));
                    t = *(__half2*)&pa_h[3];
                    pa_l[3] = pack_h2(p30 - __half2float(t.x), p31 - __half2float(t.y));
                }
                uint32_t vh[8][2], vl[8][2];
#pragma unroll
                for (int p = 0; p < 4; p++) {
                    uint32_t off = (uint32_t)((kk * 16 + v_row) * (AST * 2) + (p * 16 + v_col) * 2);
                    uint32_t r4[4];
                    ldsm_x4_t(r4, sb + SVH + off);
                    vh[p*2][0] = r4[0]; vh[p*2][1] = r4[1];
                    vh[p*2+1][0] = r4[2]; vh[p*2+1][1] = r4[3];
                    ldsm_x4_t(r4, sb + SVL + off);
                    vl[p*2][0] = r4[0]; vl[p*2][1] = r4[1];
                    vl[p*2+1][0] = r4[2]; vl[p*2+1][1] = r4[3];
                }
#pragma unroll
                for (int ni = 0; ni < 8; ni++) {
                    mma16816(o[ni], pa_h, vh[ni]);
                    mma16816(o[ni], pa_l, vh[ni]);
                    mma16816(o[ni], pa_h, vl[ni]);
                }
            }
        }
        __syncthreads();
    }

    const float inv0 = 1.0f / l0, inv1 = 1.0f / l1;
    const int gr = grow0 + wr + lr;
    const int gcb = h * DH + qc * 2;
#pragma unroll
    for (int ni = 0; ni < 8; ni++) {
        float v0 = o[ni][0] * inv0, v1 = o[ni][1] * inv0;
        float v2 = o[ni][2] * inv1, v3 = o[ni][3] * inv1;
        size_t i0 = (size_t)gr * NX + gcb + ni * 8;
        size_t i1 = (size_t)(gr + 8) * NX + gcb + ni * 8;
        uint32_t h0 = pack_h2(v0, v1);
        uint32_t h1 = pack_h2(v2, v3);
        *(uint32_t*)(ohi_ + i0) = h0;
        *(uint32_t*)(ohi_ + i1) = h1;
        __half2 t0 = *(__half2*)&h0;
        __half2 t1 = *(__half2*)&h1;
        *(uint32_t*)(olo_ + i0) = pack_h2(v0 - __half2float(t0.x), v1 - __half2float(t0.y));
        *(uint32_t*)(olo_ + i1) = pack_h2(v2 - __half2float(t1.x), v3 - __half2float(t1.y));
    }
}

// =====================================================================
// weight transpose (fp16 hi only): Wt[n][k] = fp16(W[k][n])
// =====================================================================
__global__ __launch_bounds__(256) void tsplit_kernel(
    const float* __restrict__ W, __half* __restrict__ hi, int K, int N)
{
    __shared__ float t[32][33];
    const int n0 = blockIdx.x * 32, k0 = blockIdx.y * 32;
    const int tx = threadIdx.x & 31, ty = threadIdx.x >> 5;
#pragma unroll
    for (int i = 0; i < 32; i += 8)
        t[ty + i][tx] = W[(size_t)(k0 + ty + i) * N + n0 + tx];
    __syncthreads();
#pragma unroll
    for (int i = 0; i < 32; i += 8) {
        float v = t[tx][ty + i];
        hi[(size_t)(n0 + ty + i) * K + k0 + tx] = __float2half_rn(v);
    }
}

__global__ __launch_bounds__(256) void split_kernel(
    const float* __restrict__ in, __half* __restrict__ hi,
    __half* __restrict__ lo, int n4)
{
    int i = blockIdx.x * blockDim.x + threadIdx.x;
    if (i >= n4) return;
    float4 v = *(const float4*)(in + i * 4);
    __half h0 = __float2half_rn(v.x), h1 = __float2half_rn(v.y);
    __half h2 = __float2half_rn(v.z), h3 = __float2half_rn(v.w);
    __half2 p0; p0.x = h0; p0.y = h1;
    __half2 p1; p1.x = h2; p1.y = h3;
    *(__half2*)(hi + i * 4) = p0;
    *(__half2*)(hi + i * 4 + 2) = p1;
    __half2 q0, q1;
    q0.x = __float2half_rn(v.x - __half2float(h0));
    q0.y = __float2half_rn(v.y - __half2float(h1));
    q1.x = __float2half_rn(v.z - __half2float(h2));
    q1.y = __float2half_rn(v.w - __half2float(h3));
    *(__half2*)(lo + i * 4) = q0;
    *(__half2*)(lo + i * 4 + 2) = q1;
}

// =====================================================================
// LayerNorm (additive, faithful to source bug) + optional fp16 split out
// =====================================================================
__global__ __launch_bounds__(256) void ln_kernel(
    const float* __restrict__ in1, const float* __restrict__ in2,
    const float* __restrict__ g, const float* __restrict__ bb,
    float* __restrict__ out, __half* __restrict__ ohi,
    __half* __restrict__ olo)
{
    __shared__ float buf[NX];
    __shared__ float wsum[8], wsum2[8];

    const int row = blockIdx.x;
    const int tid = threadIdx.x;
    const int lane = tid & 31;
    const int wrp = tid >> 5;
    const size_t base = (size_t)row * NX;

    float s = 0.0f, s2 = 0.0f;
#pragma unroll
    for (int k = 0; k < 3; k++) {
        int i = tid + k * 256;
        float v = in1[base + i] + in2[base + i];
        buf[i] = v;
        s += v; s2 += v * v;
    }
#pragma unroll
    for (int off = 16; off > 0; off >>= 1) {
        s  += __shfl_xor_sync(0xffffffffu, s,  off);
        s2 += __shfl_xor_sync(0xffffffffu, s2, off);
    }
    if (lane == 0) { wsum[wrp] = s; wsum2[wrp] = s2; }
    __syncthreads();
    if (wrp == 0) {
        float a = (lane < 8) ? wsum[lane] : 0.0f;
        float a2 = (lane < 8) ? wsum2[lane] : 0.0f;
#pragma unroll
        for (int off = 4; off > 0; off >>= 1) {
            a  += __shfl_xor_sync(0xffffffffu, a,  off);
            a2 += __shfl_xor_sync(0xffffffffu, a2, off);
        }
        if (lane == 0) { wsum[0] = a; wsum2[0] = a2; }
    }
    __syncthreads();
    const float u = wsum[0] * (1.0f / NX);
    const float var = wsum2[0] * (1.0f / NX) - u * u;
    const float rstd = rsqrtf(var + EPS);
#pragma unroll
    for (int k = 0; k < 3; k++) {
        int i = tid + k * 256;
        float v = g[i] + (buf[i] - u) * rstd + bb[i];
        out[base + i] = v;
        if (ohi) {
            __half h = __float2half_rn(v);
            ohi[base + i] = h;
            olo[base + i] = __float2half_rn(v - __half2float(h));
        }
    }
}

// =====================================================================
extern "C" void kernel_launch(void* const* d_in, const int* in_sizes, int n_in,
                              void* d_out, int out_size)
{
    const float* x      = (const float*)d_in[0];
    const float* w_attn = (const float*)d_in[1];
    const float* b_attn = (const float*)d_in[2];
    const float* w_proj = (const float*)d_in[3];
    const float* b_proj = (const float*)d_in[4];
    const float* ln1_g  = (const float*)d_in[5];
    const float* ln1_b  = (const float*)d_in[6];
    const float* w_fc   = (const float*)d_in[7];
    const float* b_fc   = (const float*)d_in[8];
    const float* w_fc2  = (const float*)d_in[9];
    const float* b_fc2  = (const float*)d_in[10];
    const float* ln2_g  = (const float*)d_in[11];
    const float* ln2_b  = (const float*)d_in[12];
    float* out = (float*)d_out;

    float *nbuf, *tmp;
    __half *ahi, *alo, *hhi, *hlo, *whi;
    cudaGetSymbolAddress((void**)&nbuf, g_n);
    cudaGetSymbolAddress((void**)&tmp,  g_tmp);
    cudaGetSymbolAddress((void**)&ahi,  g_ahi);
    cudaGetSymbolAddress((void**)&alo,  g_alo);
    cudaGetSymbolAddress((void**)&hhi,  g_hhi);
    cudaGetSymbolAddress((void**)&hlo,  g_hlo);
    cudaGetSymbolAddress((void**)&whi,  g_whi);

    static int smem_set = 0;
    if (!smem_set) {
        cudaFuncSetAttribute(gemm_tc_kernel,
                             cudaFuncAttributeMaxDynamicSharedMemorySize, GEMM_DSMEM);
        cudaFuncSetAttribute(attn_mma_kernel,
                             cudaFuncAttributeMaxDynamicSharedMemorySize, ATTN_DSMEM);
        smem_set = 1;
    }

    // --- weight prep (fp16 hi only) ---
    tsplit_kernel<<<dim3(3 * NX / 32, NX / 32), 256>>>(w_attn, whi + WOFF_ATTN, NX, 3 * NX);
    tsplit_kernel<<<dim3(NX / 32, NX / 32),     256>>>(w_proj, whi + WOFF_PROJ, NX, NX);
    tsplit_kernel<<<dim3(4 * NX / 32, NX / 32), 256>>>(w_fc,   whi + WOFF_FC,   NX, 4 * NX);
    tsplit_kernel<<<dim3(NX / 32, 4 * NX / 32), 256>>>(w_fc2,  whi + WOFF_FC2,  4 * NX, NX);

    // --- x split ---
    split_kernel<<<(MROWS * NX / 4 + 255) / 256, 256>>>(x, ahi, alo, MROWS * NX / 4);

    // 1. qkv = x @ w_attn + b_attn  -> fp16 hi/lo directly
    gemm_tc_kernel<<<dim3(3 * NX / 128, MROWS / 128), 256, GEMM_DSMEM>>>(
        ahi, alo, whi + WOFF_ATTN, b_attn, nullptr, hhi, hlo,
        MROWS, 3 * NX, NX, 0);

    // 2. attention (HMMA flash, 3-term) -> attn split
    attn_mma_kernel<<<dim3(NCTX / 128, NHEAD, BATCH), 256, ATTN_DSMEM>>>(
        hhi, hlo, ahi, alo);

    // 3. proj = attn @ w_proj + b_proj -> tmp fp32
    gemm_tc_kernel<<<dim3(NX / 128, MROWS / 128), 256, GEMM_DSMEM>>>(
        ahi, alo, whi + WOFF_PROJ, b_proj, tmp, nullptr, nullptr,
        MROWS, NX, NX, 0);

    // 4. n = LN(x + proj) (+ split)
    ln_kernel<<<MROWS, 256>>>(x, tmp, ln1_g, ln1_b, nbuf, ahi, alo);

    // 5. h = relu(n @ w_fc + b_fc) -> split only
    gemm_tc_kernel<<<dim3(4 * NX / 128, MROWS / 128), 256, GEMM_DSMEM>>>(
        ahi, alo, whi + WOFF_FC, b_fc, nullptr, hhi, hlo,
        MROWS, 4 * NX, NX, 1);

    // 6. m = h @ w_fc2 + b_fc2 -> tmp
    gemm_tc_kernel<<<dim3(NX / 128, MROWS / 128), 256, GEMM_DSMEM>>>(
        hhi, hlo, whi + WOFF_FC2, b_fc2, tmp, nullptr, nullptr,
        MROWS, NX, 4 * NX, 0);

    // 7. out = LN(n + m)
    ln_kernel<<<MROWS, 256>>>(nbuf, tmp, ln2_g, ln2_b, out, nullptr, nullptr);
}